// round 1
// baseline (speedup 1.0000x reference)
#include <cuda_runtime.h>
#include <cuda_bf16.h>
#include <math.h>

// Problem dims (compile-time)
#define BB 4
#define TT 2048
#define CC 1024
#define MTOT (BB*TT)   // 8192

// SGEMM tiling
#define BM 128
#define BN 128
#define BK 8
#define TM 8
#define TN 8
#define NTHREADS 256

#define SCALE 0.03125f  // 1/sqrt(1024)

// Scratch (device globals; no allocation allowed)
__device__ float g_q[MTOT * CC];          // 32 MB
__device__ float g_k[MTOT * CC];          // 32 MB
__device__ float g_v[MTOT * CC];          // 32 MB
__device__ float g_s[BB * TT * TT];       // 64 MB  (scores -> probs in place)

// ---------------------------------------------------------------------------
// Generic 128x128x8 SGEMM body as a macro-free inline: we write it out per
// kernel because operand layouts differ (B vs B^T, k-loop bounds, bias, scale).
// ---------------------------------------------------------------------------

// Y[M,N] = X[M,K] @ W[K,N] + bias[N]; M=8192, N=K=1024. sel picks q/k/v output.
__global__ __launch_bounds__(NTHREADS, 2)
void qkv_gemm_kernel(const float* __restrict__ X, const float* __restrict__ W,
                     const float* __restrict__ bias, int sel) {
    const int N = CC, K = CC;
    float* __restrict__ Y = (sel == 0) ? g_q : (sel == 1) ? g_k : g_v;

    __shared__ float As[BK][BM];
    __shared__ float Bs[BK][BN];

    const int tid = threadIdx.x;
    const int bx = blockIdx.x;   // n tile
    const int by = blockIdx.y;   // m tile

    const int aRow = tid >> 1;          // 0..127
    const int aCol = (tid & 1) * 4;     // 0 or 4
    const int bRow = tid >> 5;          // 0..7
    const int bCol = (tid & 31) * 4;    // 0..124

    const int tx = tid & 15;
    const int ty = tid >> 4;

    const float* Aptr = X + (size_t)(by * BM) * K;
    const float* Bptr = W + bx * BN;

    float acc[TM][TN];
#pragma unroll
    for (int i = 0; i < TM; i++)
#pragma unroll
        for (int j = 0; j < TN; j++) acc[i][j] = 0.f;

    for (int k0 = 0; k0 < K; k0 += BK) {
        float4 a4 = *(const float4*)(Aptr + (size_t)aRow * K + k0 + aCol);
        As[aCol + 0][aRow] = a4.x;
        As[aCol + 1][aRow] = a4.y;
        As[aCol + 2][aRow] = a4.z;
        As[aCol + 3][aRow] = a4.w;
        *(float4*)&Bs[bRow][bCol] =
            *(const float4*)(Bptr + (size_t)(k0 + bRow) * N + bCol);
        __syncthreads();
#pragma unroll
        for (int k = 0; k < BK; k++) {
            float ra[TM], rb[TN];
#pragma unroll
            for (int i = 0; i < TM; i++) ra[i] = As[k][ty * TM + i];
#pragma unroll
            for (int j = 0; j < TN; j++) rb[j] = Bs[k][tx * TN + j];
#pragma unroll
            for (int i = 0; i < TM; i++)
#pragma unroll
                for (int j = 0; j < TN; j++) acc[i][j] = fmaf(ra[i], rb[j], acc[i][j]);
        }
        __syncthreads();
    }

#pragma unroll
    for (int i = 0; i < TM; i++) {
        const int m = by * BM + ty * TM + i;
#pragma unroll
        for (int j = 0; j < TN; j++) {
            const int n = bx * BN + tx * TN + j;
            Y[(size_t)m * N + n] = acc[i][j] + bias[n];
        }
    }
}

// S[b,t,s] = scale * sum_c q[b,t,c] * k[b,s,c]   (A @ B^T)
// Skip tiles strictly above the block diagonal (never read downstream).
__global__ __launch_bounds__(NTHREADS, 2)
void scores_kernel() {
    const int bx = blockIdx.x;   // s tile
    const int by = blockIdx.y;   // t tile
    if (bx > by) return;         // strictly above diagonal: unused
    const int z = blockIdx.z;

    __shared__ float As[BK][BM];
    __shared__ float Bs[BK][BN];

    const int tid = threadIdx.x;
    const int aRow = tid >> 1;
    const int aCol = (tid & 1) * 4;
    const int tx = tid & 15;
    const int ty = tid >> 4;

    const float* Q = g_q + (size_t)z * TT * CC + (size_t)(by * BM) * CC;
    const float* Kp = g_k + (size_t)z * TT * CC + (size_t)(bx * BN) * CC;
    float* S = g_s + (size_t)z * TT * TT;

    float acc[TM][TN];
#pragma unroll
    for (int i = 0; i < TM; i++)
#pragma unroll
        for (int j = 0; j < TN; j++) acc[i][j] = 0.f;

    for (int k0 = 0; k0 < CC; k0 += BK) {
        float4 a4 = *(const float4*)(Q + (size_t)aRow * CC + k0 + aCol);
        As[aCol + 0][aRow] = a4.x;
        As[aCol + 1][aRow] = a4.y;
        As[aCol + 2][aRow] = a4.z;
        As[aCol + 3][aRow] = a4.w;
        // B^T: rows of K-matrix are the n dimension
        float4 b4 = *(const float4*)(Kp + (size_t)aRow * CC + k0 + aCol);
        Bs[aCol + 0][aRow] = b4.x;
        Bs[aCol + 1][aRow] = b4.y;
        Bs[aCol + 2][aRow] = b4.z;
        Bs[aCol + 3][aRow] = b4.w;
        __syncthreads();
#pragma unroll
        for (int k = 0; k < BK; k++) {
            float ra[TM], rb[TN];
#pragma unroll
            for (int i = 0; i < TM; i++) ra[i] = As[k][ty * TM + i];
#pragma unroll
            for (int j = 0; j < TN; j++) rb[j] = Bs[k][tx * TN + j];
#pragma unroll
            for (int i = 0; i < TM; i++)
#pragma unroll
                for (int j = 0; j < TN; j++) acc[i][j] = fmaf(ra[i], rb[j], acc[i][j]);
        }
        __syncthreads();
    }

#pragma unroll
    for (int i = 0; i < TM; i++) {
        const int t = by * BM + ty * TM + i;
#pragma unroll
        for (int j = 0; j < TN; j++) {
            const int s = bx * BN + tx * TN + j;
            S[(size_t)t * TT + s] = acc[i][j] * SCALE;
        }
    }
}

// Causal softmax row-wise, in place. Writes zeros for s in (t, tileEnd) so the
// PV GEMM can read whole 128-wide K-tiles up to the diagonal tile.
__global__ __launch_bounds__(256)
void softmax_kernel() {
    const int row = blockIdx.x;           // 0 .. B*T-1
    const int z = row >> 11;              // /2048
    const int t = row & (TT - 1);
    float* __restrict__ Srow = g_s + (size_t)z * TT * TT + (size_t)t * TT;
    const int n = t + 1;

    __shared__ float sh[TT];
    __shared__ float red[256];
    const int tid = threadIdx.x;

    float mx = -INFINITY;
    for (int s = tid; s < n; s += 256) {
        float vv = Srow[s];
        sh[s] = vv;
        mx = fmaxf(mx, vv);
    }
    red[tid] = mx;
    __syncthreads();
    for (int off = 128; off > 0; off >>= 1) {
        if (tid < off) red[tid] = fmaxf(red[tid], red[tid + off]);
        __syncthreads();
    }
    mx = red[0];
    __syncthreads();

    float sum = 0.f;
    for (int s = tid; s < n; s += 256) {
        float e = __expf(sh[s] - mx);
        sh[s] = e;
        sum += e;
    }
    red[tid] = sum;
    __syncthreads();
    for (int off = 128; off > 0; off >>= 1) {
        if (tid < off) red[tid] += red[tid + off];
        __syncthreads();
    }
    const float inv = 1.f / red[0];

    const int zEnd = ((t >> 7) + 1) << 7;   // next multiple of 128 past t
    for (int s = tid; s < zEnd; s += 256)
        Srow[s] = (s < n) ? sh[s] * inv : 0.f;
}

// O[b,t,c] = sum_s P[b,t,s] * v[b,s,c]; K-loop truncated at (by+1)*BM.
__global__ __launch_bounds__(NTHREADS, 2)
void pv_kernel(float* __restrict__ Out) {
    const int bx = blockIdx.x;   // c tile
    const int by = blockIdx.y;   // t tile
    const int z = blockIdx.z;

    __shared__ float As[BK][BM];
    __shared__ float Bs[BK][BN];

    const int tid = threadIdx.x;
    const int aRow = tid >> 1;
    const int aCol = (tid & 1) * 4;
    const int bRow = tid >> 5;
    const int bCol = (tid & 31) * 4;
    const int tx = tid & 15;
    const int ty = tid >> 4;

    const float* P = g_s + (size_t)z * TT * TT + (size_t)(by * BM) * TT;
    const float* V = g_v + (size_t)z * TT * CC + bx * BN;
    float* O = Out + (size_t)z * TT * CC;

    float acc[TM][TN];
#pragma unroll
    for (int i = 0; i < TM; i++)
#pragma unroll
        for (int j = 0; j < TN; j++) acc[i][j] = 0.f;

    const int kmax = (by + 1) * BM;   // causal truncation
    for (int k0 = 0; k0 < kmax; k0 += BK) {
        float4 a4 = *(const float4*)(P + (size_t)aRow * TT + k0 + aCol);
        As[aCol + 0][aRow] = a4.x;
        As[aCol + 1][aRow] = a4.y;
        As[aCol + 2][aRow] = a4.z;
        As[aCol + 3][aRow] = a4.w;
        *(float4*)&Bs[bRow][bCol] =
            *(const float4*)(V + (size_t)(k0 + bRow) * CC + bCol);
        __syncthreads();
#pragma unroll
        for (int k = 0; k < BK; k++) {
            float ra[TM], rb[TN];
#pragma unroll
            for (int i = 0; i < TM; i++) ra[i] = As[k][ty * TM + i];
#pragma unroll
            for (int j = 0; j < TN; j++) rb[j] = Bs[k][tx * TN + j];
#pragma unroll
            for (int i = 0; i < TM; i++)
#pragma unroll
                for (int j = 0; j < TN; j++) acc[i][j] = fmaf(ra[i], rb[j], acc[i][j]);
        }
        __syncthreads();
    }

#pragma unroll
    for (int i = 0; i < TM; i++) {
        const int t = by * BM + ty * TM + i;
#pragma unroll
        for (int j = 0; j < TN; j++) {
            const int c = bx * BN + tx * TN + j;
            O[(size_t)t * CC + c] = acc[i][j];
        }
    }
}

extern "C" void kernel_launch(void* const* d_in, const int* in_sizes, int n_in,
                              void* d_out, int out_size) {
    const float* x  = (const float*)d_in[0];
    const float* Wq = (const float*)d_in[1];
    const float* bq = (const float*)d_in[2];
    const float* Wk = (const float*)d_in[3];
    const float* bk = (const float*)d_in[4];
    const float* Wv = (const float*)d_in[5];
    const float* bv = (const float*)d_in[6];
    float* out = (float*)d_out;

    dim3 blk(NTHREADS);
    dim3 gProj(CC / BN, MTOT / BM);          // (8, 64)
    qkv_gemm_kernel<<<gProj, blk>>>(x, Wq, bq, 0);
    qkv_gemm_kernel<<<gProj, blk>>>(x, Wk, bk, 1);
    qkv_gemm_kernel<<<gProj, blk>>>(x, Wv, bv, 2);

    dim3 gS(TT / BN, TT / BM, BB);           // (16, 16, 4)
    scores_kernel<<<gS, blk>>>();

    softmax_kernel<<<BB * TT, 256>>>();      // 8192 blocks

    dim3 gO(CC / BN, TT / BM, BB);           // (8, 16, 4)
    pv_kernel<<<gO, blk>>>(out);
}

// round 3
// speedup vs baseline: 7.0907x; 7.0907x over previous
#include <cuda_runtime.h>
#include <cuda_fp16.h>
#include <cstdint>
#include <math.h>

#define BB 4
#define TT 2048
#define CC 1024
#define MTOT (BB*TT)
#define SCALE 0.03125f

#define NTH 256
#define STAGE_B 16384      // A 8KB + B 8KB per stage
#define STAGES 3
#define DYN_B (STAGES*STAGE_B)   // 49152

// ------------------------- device scratch (no allocs) -----------------------
__device__ __half g_xh[MTOT*CC];                    // x fp16
__device__ __half g_wt[3*CC*CC];                    // W^T fp16  [n][k]
__device__ __half g_qh[MTOT*CC];
__device__ __half g_kh[MTOT*CC];
__device__ __half g_vt[(size_t)BB*CC*TT];           // V^T per batch [c][token]
__device__ float  g_s[(size_t)BB*TT*TT];            // scores fp32
__device__ __half g_ph[(size_t)BB*TT*TT];           // probs fp16

// ------------------------- ptx helpers --------------------------------------
__device__ __forceinline__ uint32_t smem_u32(const void* p) {
    uint32_t a;
    asm("{ .reg .u64 t; cvta.to.shared.u64 t, %1; cvt.u32.u64 %0, t; }" : "=r"(a) : "l"(p));
    return a;
}
#define CP_ASYNC16(dst, src) \
    asm volatile("cp.async.cg.shared.global [%0], [%1], 16;" :: "r"(dst), "l"(src))
#define CP_COMMIT() asm volatile("cp.async.commit_group;" ::: "memory")
#define CP_WAIT(n)  asm volatile("cp.async.wait_group %0;" :: "n"(n) : "memory")
#define LDSM4(r0,r1,r2,r3,addr) \
    asm volatile("ldmatrix.sync.aligned.m8n8.x4.shared.b16 {%0,%1,%2,%3}, [%4];" \
        : "=r"(r0),"=r"(r1),"=r"(r2),"=r"(r3) : "r"(addr))
#define MMA16816(c, a, b0, b1) \
    asm volatile("mma.sync.aligned.m16n8k16.row.col.f32.f16.f16.f32 " \
        "{%0,%1,%2,%3}, {%4,%5,%6,%7}, {%8,%9}, {%0,%1,%2,%3};" \
        : "+f"((c)[0]), "+f"((c)[1]), "+f"((c)[2]), "+f"((c)[3]) \
        : "r"((a)[0]), "r"((a)[1]), "r"((a)[2]), "r"((a)[3]), "r"(b0), "r"(b1))

// swizzle: 64B rows, 4x16B segs; seg ^= (row>>1)&3  (conflict-free for both
// the cp.async 16B fills and every 8-lane ldmatrix phase)
__device__ __forceinline__ uint32_t swz(uint32_t row, uint32_t byteoff) {
    uint32_t seg = (byteoff >> 4) ^ ((row >> 1) & 3);
    return row * 64 + (seg << 4) + (byteoff & 15);
}

// ------------------------- converts -----------------------------------------
__global__ void convert_x_kernel(const float* __restrict__ x) {
    size_t i = (size_t)blockIdx.x * 256 + threadIdx.x;   // one float4 each
    float4 v = ((const float4*)x)[i];
    __half2 h0 = __floats2half2_rn(v.x, v.y);
    __half2 h1 = __floats2half2_rn(v.z, v.w);
    uint2 o = make_uint2(*(uint32_t*)&h0, *(uint32_t*)&h1);
    ((uint2*)g_xh)[i] = o;
}

// W[k][n] -> wt[n][k] fp16
__global__ void convert_w_kernel(const float* __restrict__ W, int sel) {
    __shared__ float tile[32][33];
    int bx = blockIdx.x * 32, by = blockIdx.y * 32;
    int tx = threadIdx.x, ty = threadIdx.y;    // 32 x 8
#pragma unroll
    for (int r = 0; r < 4; r++)
        tile[ty + 8*r][tx] = W[(size_t)(by + ty + 8*r) * CC + bx + tx];
    __syncthreads();
    __half* dst = g_wt + (size_t)sel * CC * CC;
#pragma unroll
    for (int r = 0; r < 4; r++)
        dst[(size_t)(bx + ty + 8*r) * CC + by + tx] = __float2half(tile[tx][ty + 8*r]);
}

// ------------------------- pipelined MMA mainloop ----------------------------
__device__ __forceinline__ void issue_stage(uint32_t sm, int stage,
                                            const __half* __restrict__ Ag, int lda,
                                            const __half* __restrict__ Bg, int ldb, int k0) {
    const int tid = threadIdx.x;
    uint32_t sb = sm + stage * STAGE_B;
#pragma unroll
    for (int i = 0; i < 2; i++) {
        int c = tid + i * 256;                 // 512 chunks of 16B for A
        int row = c >> 2, seg = c & 3;
        CP_ASYNC16(sb + swz(row, seg * 16), Ag + (size_t)row * lda + k0 + seg * 8);
    }
#pragma unroll
    for (int i = 0; i < 2; i++) {
        int c = tid + i * 256;
        int row = c >> 2, seg = c & 3;
        CP_ASYNC16(sb + 8192 + swz(row, seg * 16), Bg + (size_t)row * ldb + k0 + seg * 8);
    }
}

// acc[2][8][4]: warp tile 32(m) x 64(n); warps 4x2 (m x n)
__device__ __forceinline__ void gemm_mainloop(uint32_t sm,
                                              const __half* __restrict__ Ag, int lda,
                                              const __half* __restrict__ Bg, int ldb,
                                              int nK, float acc[2][8][4]) {
    const int tid  = threadIdx.x;
    const int warp = tid >> 5, lane = tid & 31;
    const int wm = warp & 3, wn = warp >> 2;
    const int m0w = wm * 32, n0w = wn * 64;

    // ldmatrix lane addresses (byte offsets within a stage)
    uint32_t aOff[2][2], bOff[4][2];
#pragma unroll
    for (int mt = 0; mt < 2; mt++)
#pragma unroll
        for (int kk = 0; kk < 2; kk++) {
            uint32_t row = m0w + mt * 16 + (lane & 15);
            uint32_t bo  = kk * 32 + ((lane >> 4) & 1) * 16;
            aOff[mt][kk] = swz(row, bo);
        }
#pragma unroll
    for (int n16 = 0; n16 < 4; n16++)
#pragma unroll
        for (int kk = 0; kk < 2; kk++) {
            uint32_t row = n0w + n16 * 16 + ((lane >> 4) & 1) * 8 + (lane & 7);
            uint32_t bo  = kk * 32 + ((lane >> 3) & 1) * 16;
            bOff[n16][kk] = 8192 + swz(row, bo);
        }

    issue_stage(sm, 0, Ag, lda, Bg, ldb, 0);  CP_COMMIT();
    issue_stage(sm, 1, Ag, lda, Bg, ldb, 32); CP_COMMIT();

    for (int ks = 0; ks < nK; ks++) {
        CP_WAIT(1);
        __syncthreads();
        if (ks + 2 < nK) issue_stage(sm, (ks + 2) % 3, Ag, lda, Bg, ldb, (ks + 2) * 32);
        CP_COMMIT();

        uint32_t so = sm + (ks % 3) * STAGE_B;
#pragma unroll
        for (int kk = 0; kk < 2; kk++) {
            uint32_t a[2][4], b[4][4];
#pragma unroll
            for (int mt = 0; mt < 2; mt++)
                LDSM4(a[mt][0], a[mt][1], a[mt][2], a[mt][3], so + aOff[mt][kk]);
#pragma unroll
            for (int n16 = 0; n16 < 4; n16++)
                LDSM4(b[n16][0], b[n16][1], b[n16][2], b[n16][3], so + bOff[n16][kk]);
#pragma unroll
            for (int mt = 0; mt < 2; mt++)
#pragma unroll
                for (int n16 = 0; n16 < 4; n16++) {
                    MMA16816(acc[mt][2*n16],     a[mt], b[n16][0], b[n16][1]);
                    MMA16816(acc[mt][2*n16 + 1], a[mt], b[n16][2], b[n16][3]);
                }
        }
    }
    CP_WAIT(0);
    __syncthreads();
}

#define EPI_COORDS() \
    const int warp = threadIdx.x >> 5, lane = threadIdx.x & 31; \
    const int m0w = (warp & 3) * 32, n0w = (warp >> 2) * 64; \
    const int gm = lane >> 2, np = (lane & 3) * 2;

// ------------------------- qkv projection -----------------------------------
__global__ __launch_bounds__(NTH)
void qkv_mma_kernel(const float* __restrict__ bias, int sel) {
    extern __shared__ char dynsm[];
    uint32_t sm = smem_u32(dynsm);
    const int bx = blockIdx.x, by = blockIdx.y;  // n-tile, m-tile
    const int row0 = by * 128, col0 = bx * 128;

    float acc[2][8][4];
#pragma unroll
    for (int i = 0; i < 2; i++)
#pragma unroll
        for (int j = 0; j < 8; j++)
#pragma unroll
            for (int q = 0; q < 4; q++) acc[i][j][q] = 0.f;

    const __half* Ag = g_xh + (size_t)row0 * CC;
    const __half* Bg = g_wt + (size_t)sel * CC * CC + (size_t)col0 * CC;
    gemm_mainloop(sm, Ag, CC, Bg, CC, CC / 32, acc);

    EPI_COORDS();
    if (sel != 2) {
        __half* O = (sel == 0 ? g_qh : g_kh);
#pragma unroll
        for (int mt = 0; mt < 2; mt++)
#pragma unroll
            for (int nt = 0; nt < 8; nt++) {
                int n = n0w + nt * 8 + np;
                float b0 = __ldg(bias + col0 + n), b1 = __ldg(bias + col0 + n + 1);
                int m = m0w + mt * 16 + gm;
                __half2 h0 = __floats2half2_rn(acc[mt][nt][0] + b0, acc[mt][nt][1] + b1);
                __half2 h1 = __floats2half2_rn(acc[mt][nt][2] + b0, acc[mt][nt][3] + b1);
                *(uint32_t*)(O + (size_t)(row0 + m) * CC + col0 + n)     = *(uint32_t*)&h0;
                *(uint32_t*)(O + (size_t)(row0 + m + 8) * CC + col0 + n) = *(uint32_t*)&h1;
            }
    } else {
        // V: transpose via smem staging -> g_vt[c][token]
        __half* stage = (__half*)dynsm;          // [128][136]
#pragma unroll
        for (int mt = 0; mt < 2; mt++)
#pragma unroll
            for (int nt = 0; nt < 8; nt++) {
                int n = n0w + nt * 8 + np;
                float b0 = __ldg(bias + col0 + n), b1 = __ldg(bias + col0 + n + 1);
                int m = m0w + mt * 16 + gm;
                stage[(size_t)n * 136 + m]           = __float2half(acc[mt][nt][0] + b0);
                stage[(size_t)(n + 1) * 136 + m]     = __float2half(acc[mt][nt][1] + b1);
                stage[(size_t)n * 136 + m + 8]       = __float2half(acc[mt][nt][2] + b0);
                stage[(size_t)(n + 1) * 136 + m + 8] = __float2half(acc[mt][nt][3] + b1);
            }
        __syncthreads();
        const int z = row0 >> 11, tok0 = row0 & (TT - 1);
        const int r = threadIdx.x >> 1, half16 = (threadIdx.x & 1) * 8;
        const uint4* srcrow = (const uint4*)(stage + (size_t)r * 136);
        __half* dst = g_vt + ((size_t)z * CC + col0 + r) * TT + tok0;
#pragma unroll
        for (int i = 0; i < 8; i++) {
            int chunk = half16 + i;
            ((uint4*)dst)[chunk] = srcrow[chunk];
        }
    }
}

// ------------------------- scores -------------------------------------------
__global__ __launch_bounds__(NTH)
void scores_mma_kernel() {
    const int bx = blockIdx.x, by = blockIdx.y, z = blockIdx.z;
    if (bx > by) return;                        // causal tile skip
    extern __shared__ char dynsm[];
    uint32_t sm = smem_u32(dynsm);
    const int t0 = by * 128, s0 = bx * 128;

    float acc[2][8][4];
#pragma unroll
    for (int i = 0; i < 2; i++)
#pragma unroll
        for (int j = 0; j < 8; j++)
#pragma unroll
            for (int q = 0; q < 4; q++) acc[i][j][q] = 0.f;

    const __half* Ag = g_qh + ((size_t)z * TT + t0) * CC;
    const __half* Bg = g_kh + ((size_t)z * TT + s0) * CC;
    gemm_mainloop(sm, Ag, CC, Bg, CC, CC / 32, acc);

    EPI_COORDS();
    float* S = g_s + ((size_t)z * TT + t0) * TT + s0;
#pragma unroll
    for (int mt = 0; mt < 2; mt++)
#pragma unroll
        for (int nt = 0; nt < 8; nt++) {
            int m = m0w + mt * 16 + gm, n = n0w + nt * 8 + np;
            float2 v0 = make_float2(acc[mt][nt][0] * SCALE, acc[mt][nt][1] * SCALE);
            float2 v1 = make_float2(acc[mt][nt][2] * SCALE, acc[mt][nt][3] * SCALE);
            *(float2*)(S + (size_t)m * TT + n)       = v0;
            *(float2*)(S + (size_t)(m + 8) * TT + n) = v1;
        }
}

// ------------------------- softmax -> P fp16 ---------------------------------
__global__ __launch_bounds__(256)
void softmax_kernel() {
    const int row = blockIdx.x;
    const int z = row >> 11;
    const int t = row & (TT - 1);
    const size_t off = ((size_t)z * TT + t) * TT;
    const float* __restrict__ Srow = g_s + off;
    const int n = t + 1;

    __shared__ float sh[TT];
    __shared__ float red[256];
    const int tid = threadIdx.x;

    float mx = -INFINITY;
    for (int s = tid; s < n; s += 256) {
        float vv = Srow[s];
        sh[s] = vv;
        mx = fmaxf(mx, vv);
    }
    red[tid] = mx;
    __syncthreads();
    for (int o = 128; o > 0; o >>= 1) {
        if (tid < o) red[tid] = fmaxf(red[tid], red[tid + o]);
        __syncthreads();
    }
    mx = red[0];
    __syncthreads();

    float sum = 0.f;
    for (int s = tid; s < n; s += 256) {
        float e = __expf(sh[s] - mx);
        sh[s] = e;
        sum += e;
    }
    red[tid] = sum;
    __syncthreads();
    for (int o = 128; o > 0; o >>= 1) {
        if (tid < o) red[tid] += red[tid + o];
        __syncthreads();
    }
    const float inv = 1.f / red[0];

    const int zEnd = ((t >> 7) + 1) << 7;       // fill to 128-tile boundary
    for (int s = tid; s < zEnd; s += 256)
        g_ph[off + s] = __float2half((s < n) ? sh[s] * inv : 0.f);
}

// ------------------------- P @ V ---------------------------------------------
__global__ __launch_bounds__(NTH)
void pv_mma_kernel(float* __restrict__ Out) {
    const int bx = blockIdx.x, by = blockIdx.y, z = blockIdx.z;  // c-tile, t-tile
    extern __shared__ char dynsm[];
    uint32_t sm = smem_u32(dynsm);
    const int t0 = by * 128, c0 = bx * 128;

    float acc[2][8][4];
#pragma unroll
    for (int i = 0; i < 2; i++)
#pragma unroll
        for (int j = 0; j < 8; j++)
#pragma unroll
            for (int q = 0; q < 4; q++) acc[i][j][q] = 0.f;

    const __half* Ag = g_ph + ((size_t)z * TT + t0) * TT;
    const __half* Bg = g_vt + ((size_t)z * CC + c0) * TT;
    gemm_mainloop(sm, Ag, TT, Bg, TT, (by + 1) * 4, acc);   // causal truncation

    EPI_COORDS();
    float* O = Out + ((size_t)z * TT + t0) * CC + c0;
#pragma unroll
    for (int mt = 0; mt < 2; mt++)
#pragma unroll
        for (int nt = 0; nt < 8; nt++) {
            int m = m0w + mt * 16 + gm, n = n0w + nt * 8 + np;
            *(float2*)(O + (size_t)m * CC + n)       = make_float2(acc[mt][nt][0], acc[mt][nt][1]);
            *(float2*)(O + (size_t)(m + 8) * CC + n) = make_float2(acc[mt][nt][2], acc[mt][nt][3]);
        }
}

// ------------------------- launch -------------------------------------------
extern "C" void kernel_launch(void* const* d_in, const int* in_sizes, int n_in,
                              void* d_out, int out_size) {
    const float* x  = (const float*)d_in[0];
    const float* Wq = (const float*)d_in[1];
    const float* bq = (const float*)d_in[2];
    const float* Wk = (const float*)d_in[3];
    const float* bk = (const float*)d_in[4];
    const float* Wv = (const float*)d_in[5];
    const float* bv = (const float*)d_in[6];
    float* out = (float*)d_out;

    cudaFuncSetAttribute(qkv_mma_kernel,    cudaFuncAttributeMaxDynamicSharedMemorySize, DYN_B);
    cudaFuncSetAttribute(scores_mma_kernel, cudaFuncAttributeMaxDynamicSharedMemorySize, DYN_B);
    cudaFuncSetAttribute(pv_mma_kernel,     cudaFuncAttributeMaxDynamicSharedMemorySize, DYN_B);

    convert_x_kernel<<<MTOT * CC / 4 / 256, 256>>>(x);
    convert_w_kernel<<<dim3(32, 32), dim3(32, 8)>>>(Wq, 0);
    convert_w_kernel<<<dim3(32, 32), dim3(32, 8)>>>(Wk, 1);
    convert_w_kernel<<<dim3(32, 32), dim3(32, 8)>>>(Wv, 2);

    qkv_mma_kernel<<<dim3(8, 64), NTH, DYN_B>>>(bq, 0);
    qkv_mma_kernel<<<dim3(8, 64), NTH, DYN_B>>>(bk, 1);
    qkv_mma_kernel<<<dim3(8, 64), NTH, DYN_B>>>(bv, 2);

    scores_mma_kernel<<<dim3(16, 16, 4), NTH, DYN_B>>>();
    softmax_kernel<<<BB * TT, 256>>>();
    pv_mma_kernel<<<dim3(8, 16, 4), NTH, DYN_B>>>(out);
}

// round 4
// speedup vs baseline: 8.2033x; 1.1569x over previous
#include <cuda_runtime.h>
#include <cuda_fp16.h>
#include <cstdint>
#include <math.h>

#define BB 4
#define TT 2048
#define CC 1024
#define MTOT (BB*TT)
#define SCALE 0.03125f

#define NTH 256
#define STAGE_B 32768      // A 16KB + B 16KB per stage (BK=64)
#define STAGES 3
#define DYN_B (STAGES*STAGE_B)   // 98304

// ------------------------- device scratch (no allocs) -----------------------
__device__ __half g_xh[MTOT*CC];                    // x fp16
__device__ __half g_wt[3*CC*CC];                    // W^T fp16  [sel*1024+n][k]
__device__ __half g_qh[MTOT*CC];                    // q * SCALE
__device__ __half g_kh[MTOT*CC];
__device__ __half g_vt[(size_t)BB*CC*TT];           // V^T per batch [c][token]
__device__ float  g_s[(size_t)BB*TT*TT];            // scores fp32
__device__ __half g_ph[(size_t)BB*TT*TT];           // probs fp16

// ------------------------- ptx helpers --------------------------------------
__device__ __forceinline__ uint32_t smem_u32(const void* p) {
    uint32_t a;
    asm("{ .reg .u64 t; cvta.to.shared.u64 t, %1; cvt.u32.u64 %0, t; }" : "=r"(a) : "l"(p));
    return a;
}
#define CP_ASYNC16(dst, src) \
    asm volatile("cp.async.cg.shared.global [%0], [%1], 16;" :: "r"(dst), "l"(src))
#define CP_COMMIT() asm volatile("cp.async.commit_group;" ::: "memory")
#define CP_WAIT(n)  asm volatile("cp.async.wait_group %0;" :: "n"(n) : "memory")
#define LDSM4(r0,r1,r2,r3,addr) \
    asm volatile("ldmatrix.sync.aligned.m8n8.x4.shared.b16 {%0,%1,%2,%3}, [%4];" \
        : "=r"(r0),"=r"(r1),"=r"(r2),"=r"(r3) : "r"(addr))
#define MMA16816(c, a, b0, b1) \
    asm volatile("mma.sync.aligned.m16n8k16.row.col.f32.f16.f16.f32 " \
        "{%0,%1,%2,%3}, {%4,%5,%6,%7}, {%8,%9}, {%0,%1,%2,%3};" \
        : "+f"((c)[0]), "+f"((c)[1]), "+f"((c)[2]), "+f"((c)[3]) \
        : "r"((a)[0]), "r"((a)[1]), "r"((a)[2]), "r"((a)[3]), "r"(b0), "r"(b1))

// swizzle for 128B rows (64 fp16): seg(16B) ^= row&7 — conflict-free for
// cp.async 16B fills and all ldmatrix phases
__device__ __forceinline__ uint32_t swz(uint32_t row, uint32_t byteoff) {
    uint32_t seg = (byteoff >> 4) ^ (row & 7);
    return row * 128 + (seg << 4) + (byteoff & 15);
}

// ------------------------- converts -----------------------------------------
__global__ void convert_x_kernel(const float* __restrict__ x) {
    size_t i = (size_t)blockIdx.x * 256 + threadIdx.x;
    float4 v = ((const float4*)x)[i];
    __half2 h0 = __floats2half2_rn(v.x, v.y);
    __half2 h1 = __floats2half2_rn(v.z, v.w);
    ((uint2*)g_xh)[i] = make_uint2(*(uint32_t*)&h0, *(uint32_t*)&h1);
}

// W[k][n] -> wt[n][k] fp16
__global__ void convert_w_kernel(const float* __restrict__ W, int sel) {
    __shared__ float tile[32][33];
    int bx = blockIdx.x * 32, by = blockIdx.y * 32;
    int tx = threadIdx.x, ty = threadIdx.y;    // 32 x 8
#pragma unroll
    for (int r = 0; r < 4; r++)
        tile[ty + 8*r][tx] = W[(size_t)(by + ty + 8*r) * CC + bx + tx];
    __syncthreads();
    __half* dst = g_wt + (size_t)sel * CC * CC;
#pragma unroll
    for (int r = 0; r < 4; r++)
        dst[(size_t)(bx + ty + 8*r) * CC + by + tx] = __float2half(tile[tx][ty + 8*r]);
}

// ------------------------- pipelined MMA mainloop (BK=64) --------------------
__device__ __forceinline__ void issue_stage(uint32_t sm, int stage,
                                            const __half* __restrict__ Ag, int lda,
                                            const __half* __restrict__ Bg, int ldb, int k0) {
    const int tid = threadIdx.x;
    uint32_t sb = sm + stage * STAGE_B;
#pragma unroll
    for (int i = 0; i < 4; i++) {              // A: 128 rows x 8 segs of 16B
        int c = tid + i * 256;
        int row = c >> 3, seg = c & 7;
        CP_ASYNC16(sb + swz(row, seg * 16), Ag + (size_t)row * lda + k0 + seg * 8);
    }
#pragma unroll
    for (int i = 0; i < 4; i++) {              // B
        int c = tid + i * 256;
        int row = c >> 3, seg = c & 7;
        CP_ASYNC16(sb + 16384 + swz(row, seg * 16), Bg + (size_t)row * ldb + k0 + seg * 8);
    }
}

// acc[2][8][4]: warp tile 32(m) x 64(n); warps 4x2 (m x n)
__device__ __forceinline__ void gemm_mainloop(uint32_t sm,
                                              const __half* __restrict__ Ag, int lda,
                                              const __half* __restrict__ Bg, int ldb,
                                              int nK, float acc[2][8][4]) {
    const int tid  = threadIdx.x;
    const int warp = tid >> 5, lane = tid & 31;
    const int m0w = (warp & 3) * 32, n0w = (warp >> 2) * 64;

    uint32_t aOff[2][4], bOff[4][4];
#pragma unroll
    for (int mt = 0; mt < 2; mt++)
#pragma unroll
        for (int kk = 0; kk < 4; kk++) {
            uint32_t row = m0w + mt * 16 + (lane & 15);
            uint32_t bo  = kk * 32 + ((lane >> 4) & 1) * 16;
            aOff[mt][kk] = swz(row, bo);
        }
#pragma unroll
    for (int n16 = 0; n16 < 4; n16++)
#pragma unroll
        for (int kk = 0; kk < 4; kk++) {
            uint32_t row = n0w + n16 * 16 + ((lane >> 4) & 1) * 8 + (lane & 7);
            uint32_t bo  = kk * 32 + ((lane >> 3) & 1) * 16;
            bOff[n16][kk] = 16384 + swz(row, bo);
        }

    issue_stage(sm, 0, Ag, lda, Bg, ldb, 0);  CP_COMMIT();
    issue_stage(sm, 1, Ag, lda, Bg, ldb, 64); CP_COMMIT();

    for (int ks = 0; ks < nK; ks++) {
        CP_WAIT(1);
        __syncthreads();
        if (ks + 2 < nK) issue_stage(sm, (ks + 2) % 3, Ag, lda, Bg, ldb, (ks + 2) * 64);
        CP_COMMIT();

        uint32_t so = sm + (ks % 3) * STAGE_B;
#pragma unroll
        for (int kk = 0; kk < 4; kk++) {
            uint32_t a[2][4], b[4][4];
#pragma unroll
            for (int mt = 0; mt < 2; mt++)
                LDSM4(a[mt][0], a[mt][1], a[mt][2], a[mt][3], so + aOff[mt][kk]);
#pragma unroll
            for (int n16 = 0; n16 < 4; n16++)
                LDSM4(b[n16][0], b[n16][1], b[n16][2], b[n16][3], so + bOff[n16][kk]);
#pragma unroll
            for (int mt = 0; mt < 2; mt++)
#pragma unroll
                for (int n16 = 0; n16 < 4; n16++) {
                    MMA16816(acc[mt][2*n16],     a[mt], b[n16][0], b[n16][1]);
                    MMA16816(acc[mt][2*n16 + 1], a[mt], b[n16][2], b[n16][3]);
                }
        }
    }
    CP_WAIT(0);
    __syncthreads();
}

#define EPI_COORDS() \
    const int warp = threadIdx.x >> 5, lane = threadIdx.x & 31; \
    const int m0w = (warp & 3) * 32, n0w = (warp >> 2) * 64; \
    const int gm = lane >> 2, np = (lane & 3) * 2;

// ------------------------- fused QKV projection ------------------------------
__global__ __launch_bounds__(NTH, 1)
void qkv_mma_kernel(const float* __restrict__ bq, const float* __restrict__ bk,
                    const float* __restrict__ bv) {
    extern __shared__ char dynsm[];
    uint32_t sm = smem_u32(dynsm);
    const int bx = blockIdx.x, by = blockIdx.y;   // n-tile (0..23), m-tile
    const int row0 = by * 128, col0 = bx * 128;   // col0 in [0, 3072)
    const int sel = bx >> 3;                      // 0=q 1=k 2=v
    const int vcol0 = col0 & 1023;
    const float* bias = (sel == 0) ? bq : (sel == 1) ? bk : bv;
    const float mul = (sel == 0) ? SCALE : 1.0f;

    float acc[2][8][4];
#pragma unroll
    for (int i = 0; i < 2; i++)
#pragma unroll
        for (int j = 0; j < 8; j++)
#pragma unroll
            for (int q = 0; q < 4; q++) acc[i][j][q] = 0.f;

    const __half* Ag = g_xh + (size_t)row0 * CC;
    const __half* Bg = g_wt + (size_t)col0 * CC;
    gemm_mainloop(sm, Ag, CC, Bg, CC, CC / 64, acc);

    EPI_COORDS();
    if (sel != 2) {
        __half* O = (sel == 0 ? g_qh : g_kh);
#pragma unroll
        for (int mt = 0; mt < 2; mt++)
#pragma unroll
            for (int nt = 0; nt < 8; nt++) {
                int n = n0w + nt * 8 + np;
                float b0 = __ldg(bias + vcol0 + n), b1 = __ldg(bias + vcol0 + n + 1);
                int m = m0w + mt * 16 + gm;
                __half2 h0 = __floats2half2_rn((acc[mt][nt][0] + b0) * mul,
                                               (acc[mt][nt][1] + b1) * mul);
                __half2 h1 = __floats2half2_rn((acc[mt][nt][2] + b0) * mul,
                                               (acc[mt][nt][3] + b1) * mul);
                *(uint32_t*)(O + (size_t)(row0 + m) * CC + vcol0 + n)     = *(uint32_t*)&h0;
                *(uint32_t*)(O + (size_t)(row0 + m + 8) * CC + vcol0 + n) = *(uint32_t*)&h1;
            }
    } else {
        // V: transpose via smem staging -> g_vt[c][token]
        __half* stage = (__half*)dynsm;          // [128][136]
#pragma unroll
        for (int mt = 0; mt < 2; mt++)
#pragma unroll
            for (int nt = 0; nt < 8; nt++) {
                int n = n0w + nt * 8 + np;
                float b0 = __ldg(bias + vcol0 + n), b1 = __ldg(bias + vcol0 + n + 1);
                int m = m0w + mt * 16 + gm;
                stage[(size_t)n * 136 + m]           = __float2half(acc[mt][nt][0] + b0);
                stage[(size_t)(n + 1) * 136 + m]     = __float2half(acc[mt][nt][1] + b1);
                stage[(size_t)n * 136 + m + 8]       = __float2half(acc[mt][nt][2] + b0);
                stage[(size_t)(n + 1) * 136 + m + 8] = __float2half(acc[mt][nt][3] + b1);
            }
        __syncthreads();
        const int z = row0 >> 11, tok0 = row0 & (TT - 1);
        const int r = threadIdx.x >> 1, half16 = (threadIdx.x & 1) * 8;
        const uint4* srcrow = (const uint4*)(stage + (size_t)r * 136);
        __half* dst = g_vt + ((size_t)z * CC + vcol0 + r) * TT + tok0;
#pragma unroll
        for (int i = 0; i < 8; i++)
            ((uint4*)dst)[half16 + i] = srcrow[half16 + i];
    }
}

// ------------------------- scores (q prescaled) ------------------------------
__global__ __launch_bounds__(NTH, 1)
void scores_mma_kernel() {
    const int bx = blockIdx.x, by = blockIdx.y, z = blockIdx.z;
    if (bx > by) return;                        // causal tile skip
    extern __shared__ char dynsm[];
    uint32_t sm = smem_u32(dynsm);
    const int t0 = by * 128, s0 = bx * 128;

    float acc[2][8][4];
#pragma unroll
    for (int i = 0; i < 2; i++)
#pragma unroll
        for (int j = 0; j < 8; j++)
#pragma unroll
            for (int q = 0; q < 4; q++) acc[i][j][q] = 0.f;

    const __half* Ag = g_qh + ((size_t)z * TT + t0) * CC;
    const __half* Bg = g_kh + ((size_t)z * TT + s0) * CC;
    gemm_mainloop(sm, Ag, CC, Bg, CC, CC / 64, acc);

    EPI_COORDS();
    float* S = g_s + ((size_t)z * TT + t0) * TT + s0;
#pragma unroll
    for (int mt = 0; mt < 2; mt++)
#pragma unroll
        for (int nt = 0; nt < 8; nt++) {
            int m = m0w + mt * 16 + gm, n = n0w + nt * 8 + np;
            *(float2*)(S + (size_t)m * TT + n)       = make_float2(acc[mt][nt][0], acc[mt][nt][1]);
            *(float2*)(S + (size_t)(m + 8) * TT + n) = make_float2(acc[mt][nt][2], acc[mt][nt][3]);
        }
}

// ------------------------- softmax: warp per row -----------------------------
__global__ __launch_bounds__(256)
void softmax_kernel() {
    extern __shared__ float shall[];            // 8 rows x 2048 floats
    const int warp = threadIdx.x >> 5, lane = threadIdx.x & 31;
    const int row = blockIdx.x * 8 + warp;
    const int z = row >> 11;
    const int t = row & (TT - 1);
    const size_t off = ((size_t)z * TT + t) * TT;
    const float4* __restrict__ S4 = (const float4*)(g_s + off);
    float* sh = shall + warp * TT;
    const int n = t + 1;
    const int nch = (n + 3) >> 2;

    float mx = -INFINITY;
    for (int c = lane; c < nch; c += 32) {
        float4 v = S4[c];
        int base = c * 4;
        if (base + 3 >= n) {                    // mask tail beyond t
            if (base + 1 >= n) v.y = -INFINITY;
            if (base + 2 >= n) v.z = -INFINITY;
            if (base + 3 >= n) v.w = -INFINITY;
        }
        ((float4*)sh)[c] = v;
        mx = fmaxf(mx, fmaxf(fmaxf(v.x, v.y), fmaxf(v.z, v.w)));
    }
#pragma unroll
    for (int o = 16; o > 0; o >>= 1)
        mx = fmaxf(mx, __shfl_xor_sync(0xFFFFFFFFu, mx, o));

    float sum = 0.f;
    for (int c = lane; c < nch; c += 32) {
        float4 v = ((float4*)sh)[c];
        v.x = __expf(v.x - mx); v.y = __expf(v.y - mx);
        v.z = __expf(v.z - mx); v.w = __expf(v.w - mx);
        ((float4*)sh)[c] = v;
        sum += v.x + v.y + v.z + v.w;
    }
#pragma unroll
    for (int o = 16; o > 0; o >>= 1)
        sum += __shfl_xor_sync(0xFFFFFFFFu, sum, o);
    const float inv = 1.f / sum;
    __syncwarp();

    const int zEnd = ((t >> 7) + 1) << 7;       // pad to 128-tile boundary
    __half* P = g_ph + off;
    for (int c = lane; c < (zEnd >> 3); c += 32) {   // 8 halves (16B) per chunk
        int i0 = c * 8;
        __half h[8];
#pragma unroll
        for (int j = 0; j < 8; j++) {
            int idx = i0 + j;
            h[j] = __float2half((idx < n) ? sh[idx] * inv : 0.f);
        }
        *(uint4*)(P + i0) = *(uint4*)h;
    }
}

// ------------------------- P @ V (heavy tiles first) -------------------------
__global__ __launch_bounds__(NTH, 1)
void pv_mma_kernel(float* __restrict__ Out) {
    const int bx = blockIdx.x, by = 15 - blockIdx.y, z = blockIdx.z;
    extern __shared__ char dynsm[];
    uint32_t sm = smem_u32(dynsm);
    const int t0 = by * 128, c0 = bx * 128;

    float acc[2][8][4];
#pragma unroll
    for (int i = 0; i < 2; i++)
#pragma unroll
        for (int j = 0; j < 8; j++)
#pragma unroll
            for (int q = 0; q < 4; q++) acc[i][j][q] = 0.f;

    const __half* Ag = g_ph + ((size_t)z * TT + t0) * TT;
    const __half* Bg = g_vt + ((size_t)z * CC + c0) * TT;
    gemm_mainloop(sm, Ag, TT, Bg, TT, (by + 1) * 2, acc);   // causal truncation

    EPI_COORDS();
    float* O = Out + ((size_t)z * TT + t0) * CC + c0;
#pragma unroll
    for (int mt = 0; mt < 2; mt++)
#pragma unroll
        for (int nt = 0; nt < 8; nt++) {
            int m = m0w + mt * 16 + gm, n = n0w + nt * 8 + np;
            *(float2*)(O + (size_t)m * CC + n)       = make_float2(acc[mt][nt][0], acc[mt][nt][1]);
            *(float2*)(O + (size_t)(m + 8) * CC + n) = make_float2(acc[mt][nt][2], acc[mt][nt][3]);
        }
}

// ------------------------- launch -------------------------------------------
extern "C" void kernel_launch(void* const* d_in, const int* in_sizes, int n_in,
                              void* d_out, int out_size) {
    const float* x  = (const float*)d_in[0];
    const float* Wq = (const float*)d_in[1];
    const float* bq = (const float*)d_in[2];
    const float* Wk = (const float*)d_in[3];
    const float* bk = (const float*)d_in[4];
    const float* Wv = (const float*)d_in[5];
    const float* bv = (const float*)d_in[6];
    float* out = (float*)d_out;

    cudaFuncSetAttribute(qkv_mma_kernel,    cudaFuncAttributeMaxDynamicSharedMemorySize, DYN_B);
    cudaFuncSetAttribute(scores_mma_kernel, cudaFuncAttributeMaxDynamicSharedMemorySize, DYN_B);
    cudaFuncSetAttribute(pv_mma_kernel,     cudaFuncAttributeMaxDynamicSharedMemorySize, DYN_B);
    cudaFuncSetAttribute(softmax_kernel,    cudaFuncAttributeMaxDynamicSharedMemorySize, 65536);

    convert_x_kernel<<<MTOT * CC / 4 / 256, 256>>>(x);
    convert_w_kernel<<<dim3(32, 32), dim3(32, 8)>>>(Wq, 0);
    convert_w_kernel<<<dim3(32, 32), dim3(32, 8)>>>(Wk, 1);
    convert_w_kernel<<<dim3(32, 32), dim3(32, 8)>>>(Wv, 2);

    qkv_mma_kernel<<<dim3(24, 64), NTH, DYN_B>>>(bq, bk, bv);

    scores_mma_kernel<<<dim3(16, 16, 4), NTH, DYN_B>>>();
    softmax_kernel<<<BB * TT / 8, 256, 65536>>>();
    pv_mma_kernel<<<dim3(8, 16, 4), NTH, DYN_B>>>(out);
}

// round 6
// speedup vs baseline: 8.3176x; 1.0139x over previous
#include <cuda_runtime.h>
#include <cuda_fp16.h>
#include <cstdint>
#include <math.h>

#define BB 4
#define TT 2048
#define CC 1024
#define MTOT (BB*TT)
#define SCALE 0.03125f

#define NTH 256
#define STAGE_B 49152      // A 16KB (128x64) + B 32KB (256x64) per stage
#define STAGES 3
#define DYN_B (STAGES*STAGE_B)   // 147456

// ------------------------- device scratch (no allocs) -----------------------
__device__ __half g_xh[MTOT*CC];                    // x fp16
__device__ __half g_wt[3*CC*CC];                    // W^T fp16  [sel*1024+n][k]
__device__ __half g_qh[MTOT*CC];                    // q * SCALE
__device__ __half g_kh[MTOT*CC];
__device__ __half g_vt[(size_t)BB*CC*TT];           // V^T per batch [c][token]
__device__ float  g_s[(size_t)BB*TT*TT];            // scores fp32
__device__ __half g_ph[(size_t)BB*TT*TT];           // probs fp16

// ------------------------- ptx helpers --------------------------------------
__device__ __forceinline__ uint32_t smem_u32(const void* p) {
    uint32_t a;
    asm("{ .reg .u64 t; cvta.to.shared.u64 t, %1; cvt.u32.u64 %0, t; }" : "=r"(a) : "l"(p));
    return a;
}
#define CP_ASYNC16(dst, src) \
    asm volatile("cp.async.cg.shared.global [%0], [%1], 16;" :: "r"(dst), "l"(src))
#define CP_COMMIT() asm volatile("cp.async.commit_group;" ::: "memory")
#define CP_WAIT(n)  asm volatile("cp.async.wait_group %0;" :: "n"(n) : "memory")
#define LDSM4(r0,r1,r2,r3,addr) \
    asm volatile("ldmatrix.sync.aligned.m8n8.x4.shared.b16 {%0,%1,%2,%3}, [%4];" \
        : "=r"(r0),"=r"(r1),"=r"(r2),"=r"(r3) : "r"(addr))
#define MMA16816(c, a, b0, b1) \
    asm volatile("mma.sync.aligned.m16n8k16.row.col.f32.f16.f16.f32 " \
        "{%0,%1,%2,%3}, {%4,%5,%6,%7}, {%8,%9}, {%0,%1,%2,%3};" \
        : "+f"((c)[0]), "+f"((c)[1]), "+f"((c)[2]), "+f"((c)[3]) \
        : "r"((a)[0]), "r"((a)[1]), "r"((a)[2]), "r"((a)[3]), "r"(b0), "r"(b1))

// swizzle for 128B rows (64 fp16): seg(16B) ^= row&7 — conflict-free for
// cp.async 16B fills and all ldmatrix phases
__device__ __forceinline__ uint32_t swz(uint32_t row, uint32_t byteoff) {
    uint32_t seg = (byteoff >> 4) ^ (row & 7);
    return row * 128 + (seg << 4) + (byteoff & 15);
}

// ------------------------- converts -----------------------------------------
__global__ void convert_x_kernel(const float* __restrict__ x) {
    size_t i = (size_t)blockIdx.x * 256 + threadIdx.x;
    float4 v = ((const float4*)x)[i];
    __half2 h0 = __floats2half2_rn(v.x, v.y);
    __half2 h1 = __floats2half2_rn(v.z, v.w);
    ((uint2*)g_xh)[i] = make_uint2(*(uint32_t*)&h0, *(uint32_t*)&h1);
}

// W[k][n] -> wt[n][k] fp16 ; blockIdx.z selects q/k/v
__global__ void convert_w_kernel(const float* __restrict__ Wq,
                                 const float* __restrict__ Wk,
                                 const float* __restrict__ Wv) {
    __shared__ float tile[32][33];
    const int sel = blockIdx.z;
    const float* W = (sel == 0) ? Wq : (sel == 1) ? Wk : Wv;
    int bx = blockIdx.x * 32, by = blockIdx.y * 32;
    int tx = threadIdx.x, ty = threadIdx.y;    // 32 x 8
#pragma unroll
    for (int r = 0; r < 4; r++)
        tile[ty + 8*r][tx] = W[(size_t)(by + ty + 8*r) * CC + bx + tx];
    __syncthreads();
    __half* dst = g_wt + (size_t)sel * CC * CC;
#pragma unroll
    for (int r = 0; r < 4; r++)
        dst[(size_t)(bx + ty + 8*r) * CC + by + tx] = __float2half(tile[tx][ty + 8*r]);
}

// ------------------------- pipelined MMA mainloop (128x256, BK=64) -----------
__device__ __forceinline__ void issue_stage(uint32_t sm, int stage,
                                            const __half* __restrict__ Ag, int lda,
                                            const __half* __restrict__ Bg, int ldb, int k0) {
    const int tid = threadIdx.x;
    uint32_t sb = sm + stage * STAGE_B;
#pragma unroll
    for (int i = 0; i < 4; i++) {              // A: 128 rows x 8 segs of 16B
        int c = tid + i * 256;
        int row = c >> 3, seg = c & 7;
        CP_ASYNC16(sb + swz(row, seg * 16), Ag + (size_t)row * lda + k0 + seg * 8);
    }
#pragma unroll
    for (int i = 0; i < 8; i++) {              // B: 256 rows
        int c = tid + i * 256;
        int row = c >> 3, seg = c & 7;
        CP_ASYNC16(sb + 16384 + swz(row, seg * 16), Bg + (size_t)row * ldb + k0 + seg * 8);
    }
}

// acc[4][8][4]: warp tile 64(m) x 64(n); warps 2x4 (m x n)
__device__ __forceinline__ void gemm_mainloop(uint32_t sm,
                                              const __half* __restrict__ Ag, int lda,
                                              const __half* __restrict__ Bg, int ldb,
                                              int nK, float acc[4][8][4]) {
    const int tid  = threadIdx.x;
    const int warp = tid >> 5, lane = tid & 31;
    const int m0w = (warp & 1) * 64, n0w = (warp >> 1) * 64;

    // per-kk base offsets; +mt*2048 / +n16*2048 folds into LDSM immediates
    uint32_t aK[4], bK[4];
#pragma unroll
    for (int kk = 0; kk < 4; kk++) {
        aK[kk] = swz(m0w + (lane & 15), kk * 32 + ((lane >> 4) & 1) * 16);
        bK[kk] = 16384 + swz(n0w + ((lane >> 4) & 1) * 8 + (lane & 7),
                             kk * 32 + ((lane >> 3) & 1) * 16);
    }

    issue_stage(sm, 0, Ag, lda, Bg, ldb, 0);  CP_COMMIT();
    issue_stage(sm, 1, Ag, lda, Bg, ldb, 64); CP_COMMIT();

    for (int ks = 0; ks < nK; ks++) {
        CP_WAIT(1);
        __syncthreads();
        if (ks + 2 < nK) issue_stage(sm, (ks + 2) % 3, Ag, lda, Bg, ldb, (ks + 2) * 64);
        CP_COMMIT();

        uint32_t so = sm + (ks % 3) * STAGE_B;
#pragma unroll
        for (int kk = 0; kk < 4; kk++) {
            uint32_t a[4][4], b[4][4];
            uint32_t abase = so + aK[kk], bbase = so + bK[kk];
#pragma unroll
            for (int mt = 0; mt < 4; mt++)
                LDSM4(a[mt][0], a[mt][1], a[mt][2], a[mt][3], abase + mt * 2048);
#pragma unroll
            for (int n16 = 0; n16 < 4; n16++)
                LDSM4(b[n16][0], b[n16][1], b[n16][2], b[n16][3], bbase + n16 * 2048);
#pragma unroll
            for (int mt = 0; mt < 4; mt++)
#pragma unroll
                for (int n16 = 0; n16 < 4; n16++) {
                    MMA16816(acc[mt][2*n16],     a[mt], b[n16][0], b[n16][1]);
                    MMA16816(acc[mt][2*n16 + 1], a[mt], b[n16][2], b[n16][3]);
                }
        }
    }
    CP_WAIT(0);
    __syncthreads();
}

#define EPI_COORDS() \
    const int warp = threadIdx.x >> 5, lane = threadIdx.x & 31; \
    const int m0w = (warp & 1) * 64, n0w = (warp >> 1) * 64; \
    const int gm = lane >> 2, np = (lane & 3) * 2;

#define ACC_INIT() \
    float acc[4][8][4]; \
    _Pragma("unroll") for (int i = 0; i < 4; i++) \
    _Pragma("unroll") for (int j = 0; j < 8; j++) \
    _Pragma("unroll") for (int q = 0; q < 4; q++) acc[i][j][q] = 0.f;

// ------------------------- fused QKV projection ------------------------------
__global__ __launch_bounds__(NTH, 1)
void qkv_mma_kernel(const float* __restrict__ bq, const float* __restrict__ bk,
                    const float* __restrict__ bv) {
    extern __shared__ char dynsm[];
    uint32_t sm = smem_u32(dynsm);
    const int bx = blockIdx.x, by = blockIdx.y;   // n-tile (0..11), m-tile
    const int row0 = by * 128, col0 = bx * 256;   // col0 in [0, 3072)
    const int sel = bx >> 2;                      // 0=q 1=k 2=v
    const int vcol0 = col0 & 1023;
    const float* bias = (sel == 0) ? bq : (sel == 1) ? bk : bv;
    const float mul = (sel == 0) ? SCALE : 1.0f;

    ACC_INIT();
    const __half* Ag = g_xh + (size_t)row0 * CC;
    const __half* Bg = g_wt + (size_t)col0 * CC;
    gemm_mainloop(sm, Ag, CC, Bg, CC, CC / 64, acc);

    EPI_COORDS();
    if (sel != 2) {
        __half* O = (sel == 0 ? g_qh : g_kh);
#pragma unroll
        for (int mt = 0; mt < 4; mt++)
#pragma unroll
            for (int nt = 0; nt < 8; nt++) {
                int n = n0w + nt * 8 + np;
                float b0 = __ldg(bias + vcol0 + n), b1 = __ldg(bias + vcol0 + n + 1);
                int m = m0w + mt * 16 + gm;
                __half2 h0 = __floats2half2_rn((acc[mt][nt][0] + b0) * mul,
                                               (acc[mt][nt][1] + b1) * mul);
                __half2 h1 = __floats2half2_rn((acc[mt][nt][2] + b0) * mul,
                                               (acc[mt][nt][3] + b1) * mul);
                *(uint32_t*)(O + (size_t)(row0 + m) * CC + vcol0 + n)     = *(uint32_t*)&h0;
                *(uint32_t*)(O + (size_t)(row0 + m + 8) * CC + vcol0 + n) = *(uint32_t*)&h1;
            }
    } else {
        // V: transpose via smem staging -> g_vt[c][token]
        __half* stage = (__half*)dynsm;          // [256][136]
#pragma unroll
        for (int mt = 0; mt < 4; mt++)
#pragma unroll
            for (int nt = 0; nt < 8; nt++) {
                int n = n0w + nt * 8 + np;
                float b0 = __ldg(bias + vcol0 + n), b1 = __ldg(bias + vcol0 + n + 1);
                int m = m0w + mt * 16 + gm;
                stage[(size_t)n * 136 + m]           = __float2half(acc[mt][nt][0] + b0);
                stage[(size_t)(n + 1) * 136 + m]     = __float2half(acc[mt][nt][1] + b1);
                stage[(size_t)n * 136 + m + 8]       = __float2half(acc[mt][nt][2] + b0);
                stage[(size_t)(n + 1) * 136 + m + 8] = __float2half(acc[mt][nt][3] + b1);
            }
        __syncthreads();
        const int z = row0 >> 11, tok0 = row0 & (TT - 1);
        // 256 c-rows of 128 token-halfs: one row per thread, 16 x 16B (= 128 halfs)
        const int r = threadIdx.x;
        const uint4* srcrow = (const uint4*)(stage + (size_t)r * 136);
        __half* dst = g_vt + ((size_t)z * CC + vcol0 + r) * TT + tok0;
#pragma unroll
        for (int i = 0; i < 16; i++)
            ((uint4*)dst)[i] = srcrow[i];
    }
}

// ------------------------- scores (q prescaled) ------------------------------
__global__ __launch_bounds__(NTH, 1)
void scores_mma_kernel() {
    const int bx = blockIdx.x, by = blockIdx.y, z = blockIdx.z;
    if (bx * 2 > by) return;                    // causal tile skip (256-wide s)
    extern __shared__ char dynsm[];
    uint32_t sm = smem_u32(dynsm);
    const int t0 = by * 128, s0 = bx * 256;

    ACC_INIT();
    const __half* Ag = g_qh + ((size_t)z * TT + t0) * CC;
    const __half* Bg = g_kh + ((size_t)z * TT + s0) * CC;
    gemm_mainloop(sm, Ag, CC, Bg, CC, CC / 64, acc);

    EPI_COORDS();
    float* S = g_s + ((size_t)z * TT + t0) * TT + s0;
#pragma unroll
    for (int mt = 0; mt < 4; mt++)
#pragma unroll
        for (int nt = 0; nt < 8; nt++) {
            int m = m0w + mt * 16 + gm, n = n0w + nt * 8 + np;
            *(float2*)(S + (size_t)m * TT + n)       = make_float2(acc[mt][nt][0], acc[mt][nt][1]);
            *(float2*)(S + (size_t)(m + 8) * TT + n) = make_float2(acc[mt][nt][2], acc[mt][nt][3]);
        }
}

// ------------------------- softmax: warp per row -----------------------------
__global__ __launch_bounds__(256)
void softmax_kernel() {
    extern __shared__ float shall[];            // 8 rows x 2048 floats
    const int warp = threadIdx.x >> 5, lane = threadIdx.x & 31;
    const int row = blockIdx.x * 8 + warp;
    const int z = row >> 11;
    const int t = row & (TT - 1);
    const size_t off = ((size_t)z * TT + t) * TT;
    const float4* __restrict__ S4 = (const float4*)(g_s + off);
    float* sh = shall + warp * TT;
    const int n = t + 1;
    const int nch = (n + 3) >> 2;

    float mx = -INFINITY;
    for (int c = lane; c < nch; c += 32) {
        float4 v = S4[c];
        int base = c * 4;
        if (base + 3 >= n) {
            if (base + 1 >= n) v.y = -INFINITY;
            if (base + 2 >= n) v.z = -INFINITY;
            if (base + 3 >= n) v.w = -INFINITY;
        }
        ((float4*)sh)[c] = v;
        mx = fmaxf(mx, fmaxf(fmaxf(v.x, v.y), fmaxf(v.z, v.w)));
    }
#pragma unroll
    for (int o = 16; o > 0; o >>= 1)
        mx = fmaxf(mx, __shfl_xor_sync(0xFFFFFFFFu, mx, o));

    float sum = 0.f;
    for (int c = lane; c < nch; c += 32) {
        float4 v = ((float4*)sh)[c];
        v.x = __expf(v.x - mx); v.y = __expf(v.y - mx);
        v.z = __expf(v.z - mx); v.w = __expf(v.w - mx);
        ((float4*)sh)[c] = v;
        sum += v.x + v.y + v.z + v.w;
    }
#pragma unroll
    for (int o = 16; o > 0; o >>= 1)
        sum += __shfl_xor_sync(0xFFFFFFFFu, sum, o);
    const float inv = 1.f / sum;
    __syncwarp();

    const int zEnd = ((t >> 7) + 1) << 7;       // pad to 128-tile boundary
    __half* P = g_ph + off;
    for (int c = lane; c < (zEnd >> 3); c += 32) {
        int i0 = c * 8;
        __half h[8];
#pragma unroll
        for (int j = 0; j < 8; j++) {
            int idx = i0 + j;
            h[j] = __float2half((idx < n) ? sh[idx] * inv : 0.f);
        }
        *(uint4*)(P + i0) = *(uint4*)h;
    }
}

// ------------------------- P @ V (heavy tiles first) -------------------------
__global__ __launch_bounds__(NTH, 1)
void pv_mma_kernel(float* __restrict__ Out) {
    const int bx = blockIdx.x, by = 15 - blockIdx.y, z = blockIdx.z;
    extern __shared__ char dynsm[];
    uint32_t sm = smem_u32(dynsm);
    const int t0 = by * 128, c0 = bx * 256;

    ACC_INIT();
    const __half* Ag = g_ph + ((size_t)z * TT + t0) * TT;
    const __half* Bg = g_vt + ((size_t)z * CC + c0) * TT;
    gemm_mainloop(sm, Ag, TT, Bg, TT, (by + 1) * 2, acc);   // causal truncation

    EPI_COORDS();
    float* O = Out + ((size_t)z * TT + t0) * CC + c0;
#pragma unroll
    for (int mt = 0; mt < 4; mt++)
#pragma unroll
        for (int nt = 0; nt < 8; nt++) {
            int m = m0w + mt * 16 + gm, n = n0w + nt * 8 + np;
            *(float2*)(O + (size_t)m * CC + n)       = make_float2(acc[mt][nt][0], acc[mt][nt][1]);
            *(float2*)(O + (size_t)(m + 8) * CC + n) = make_float2(acc[mt][nt][2], acc[mt][nt][3]);
        }
}

// ------------------------- launch -------------------------------------------
extern "C" void kernel_launch(void* const* d_in, const int* in_sizes, int n_in,
                              void* d_out, int out_size) {
    const float* x  = (const float*)d_in[0];
    const float* Wq = (const float*)d_in[1];
    const float* bq = (const float*)d_in[2];
    const float* Wk = (const float*)d_in[3];
    const float* bk = (const float*)d_in[4];
    const float* Wv = (const float*)d_in[5];
    const float* bv = (const float*)d_in[6];
    float* out = (float*)d_out;

    cudaFuncSetAttribute(qkv_mma_kernel,    cudaFuncAttributeMaxDynamicSharedMemorySize, DYN_B);
    cudaFuncSetAttribute(scores_mma_kernel, cudaFuncAttributeMaxDynamicSharedMemorySize, DYN_B);
    cudaFuncSetAttribute(pv_mma_kernel,     cudaFuncAttributeMaxDynamicSharedMemorySize, DYN_B);
    cudaFuncSetAttribute(softmax_kernel,    cudaFuncAttributeMaxDynamicSharedMemorySize, 65536);

    convert_x_kernel<<<MTOT * CC / 4 / 256, 256>>>(x);
    convert_w_kernel<<<dim3(32, 32, 3), dim3(32, 8)>>>(Wq, Wk, Wv);

    qkv_mma_kernel<<<dim3(12, 64), NTH, DYN_B>>>(bq, bk, bv);

    scores_mma_kernel<<<dim3(8, 16, 4), NTH, DYN_B>>>();
    softmax_kernel<<<BB * TT / 8, 256, 65536>>>();
    pv_mma_kernel<<<dim3(4, 16, 4), NTH, DYN_B>>>(out);
}

// round 7
// speedup vs baseline: 8.4951x; 1.0213x over previous
#include <cuda_runtime.h>
#include <cuda_fp16.h>
#include <cstdint>
#include <math.h>

#define BB 4
#define TT 2048
#define CC 1024
#define MTOT (BB*TT)
#define SCALE 0.03125f

#define NTH 256
#define STAGE_B 49152      // A 16KB (128x64) + B 32KB (256x64) per stage
#define STAGES 3
#define DYN_B (STAGES*STAGE_B + 128)   // +128 for 128B alignment of base

// ------------------------- device scratch (no allocs) -----------------------
__device__ __half g_xh[MTOT*CC];                    // x fp16
__device__ __half g_wt[3*CC*CC];                    // W^T fp16  [sel*1024+n][k]
__device__ __half g_qh[MTOT*CC];                    // q * SCALE
__device__ __half g_kh[MTOT*CC];
__device__ __half g_vt[(size_t)BB*CC*TT];           // V^T per batch [c][token]
__device__ float  g_s[(size_t)BB*TT*TT];            // scores fp32
__device__ __half g_ph[(size_t)BB*TT*TT];           // probs fp16

// ------------------------- ptx helpers --------------------------------------
__device__ __forceinline__ uint32_t smem_u32(const void* p) {
    uint32_t a;
    asm("{ .reg .u64 t; cvta.to.shared.u64 t, %1; cvt.u32.u64 %0, t; }" : "=r"(a) : "l"(p));
    return a;
}
#define CP_ASYNC16(dst, src) \
    asm volatile("cp.async.cg.shared.global [%0], [%1], 16;" :: "r"(dst), "l"(src))
#define CP_COMMIT() asm volatile("cp.async.commit_group;" ::: "memory")
#define CP_WAIT(n)  asm volatile("cp.async.wait_group %0;" :: "n"(n) : "memory")
#define LDSM4(r0,r1,r2,r3,addr) \
    asm volatile("ldmatrix.sync.aligned.m8n8.x4.shared.b16 {%0,%1,%2,%3}, [%4];" \
        : "=r"(r0),"=r"(r1),"=r"(r2),"=r"(r3) : "r"(addr))
#define MMA16816(c, a, b0, b1) \
    asm volatile("mma.sync.aligned.m16n8k16.row.col.f32.f16.f16.f32 " \
        "{%0,%1,%2,%3}, {%4,%5,%6,%7}, {%8,%9}, {%0,%1,%2,%3};" \
        : "+f"((c)[0]), "+f"((c)[1]), "+f"((c)[2]), "+f"((c)[3]) \
        : "r"((a)[0]), "r"((a)[1]), "r"((a)[2]), "r"((a)[3]), "r"(b0), "r"(b1))

// swizzle for 128B rows (64 fp16): seg(16B) ^= row&7 — conflict-free for
// cp.async 16B fills and all ldmatrix phases
__device__ __forceinline__ uint32_t swz(uint32_t row, uint32_t byteoff) {
    uint32_t seg = (byteoff >> 4) ^ (row & 7);
    return row * 128 + (seg << 4) + (byteoff & 15);
}

// ------------------------- converts -----------------------------------------
__global__ void convert_x_kernel(const float* __restrict__ x) {
    size_t i = (size_t)blockIdx.x * 256 + threadIdx.x;
    float4 v = ((const float4*)x)[i];
    __half2 h0 = __floats2half2_rn(v.x, v.y);
    __half2 h1 = __floats2half2_rn(v.z, v.w);
    ((uint2*)g_xh)[i] = make_uint2(*(uint32_t*)&h0, *(uint32_t*)&h1);
}

// W[k][n] -> wt[n][k] fp16 ; blockIdx.z selects q/k/v
__global__ void convert_w_kernel(const float* __restrict__ Wq,
                                 const float* __restrict__ Wk,
                                 const float* __restrict__ Wv) {
    __shared__ float tile[32][33];
    const int sel = blockIdx.z;
    const float* W = (sel == 0) ? Wq : (sel == 1) ? Wk : Wv;
    int bx = blockIdx.x * 32, by = blockIdx.y * 32;
    int tx = threadIdx.x, ty = threadIdx.y;    // 32 x 8
#pragma unroll
    for (int r = 0; r < 4; r++)
        tile[ty + 8*r][tx] = W[(size_t)(by + ty + 8*r) * CC + bx + tx];
    __syncthreads();
    __half* dst = g_wt + (size_t)sel * CC * CC;
#pragma unroll
    for (int r = 0; r < 4; r++)
        dst[(size_t)(bx + ty + 8*r) * CC + by + tx] = __float2half(tile[tx][ty + 8*r]);
}

// ------------------------- pipelined MMA mainloop (128x256, BK=64) -----------
__device__ __forceinline__ void issue_stage(uint32_t sm, int stage,
                                            const __half* __restrict__ Ag, int lda,
                                            const __half* __restrict__ Bg, int ldb, int k0) {
    const int tid = threadIdx.x;
    uint32_t sb = sm + stage * STAGE_B;
#pragma unroll
    for (int i = 0; i < 4; i++) {              // A: 128 rows x 8 segs of 16B
        int c = tid + i * 256;
        int row = c >> 3, seg = c & 7;
        CP_ASYNC16(sb + swz(row, seg * 16), Ag + (size_t)row * lda + k0 + seg * 8);
    }
#pragma unroll
    for (int i = 0; i < 8; i++) {              // B: 256 rows
        int c = tid + i * 256;
        int row = c >> 3, seg = c & 7;
        CP_ASYNC16(sb + 16384 + swz(row, seg * 16), Bg + (size_t)row * ldb + k0 + seg * 8);
    }
}

// load one kk's fragments into buffer `buf` from bases ab/bb
#define LDFRAGS(buf, ab, bb) do { \
    _Pragma("unroll") \
    for (int _mt = 0; _mt < 4; _mt++) \
        LDSM4(afr[buf][_mt][0], afr[buf][_mt][1], afr[buf][_mt][2], afr[buf][_mt][3], \
              (ab) + _mt * 2048); \
    _Pragma("unroll") \
    for (int _n = 0; _n < 4; _n++) \
        LDSM4(bfr[buf][_n][0], bfr[buf][_n][1], bfr[buf][_n][2], bfr[buf][_n][3], \
              (bb) + _n * 2048); \
} while (0)

// acc[4][8][4]: warp tile 64(m) x 64(n); warps 2x4 (m x n)
__device__ __forceinline__ void gemm_mainloop(uint32_t sm,
                                              const __half* __restrict__ Ag, int lda,
                                              const __half* __restrict__ Bg, int ldb,
                                              int nK, float acc[4][8][4]) {
    const int tid  = threadIdx.x;
    const int warp = tid >> 5, lane = tid & 31;
    const int m0w = (warp & 1) * 64, n0w = (warp >> 1) * 64;

    // kk=0 base offsets; addr(kk) = base ^ (kk<<5)  (seg-field XOR identity;
    // requires sm 128B-aligned and STAGE_B % 128 == 0)
    const uint32_t aK0 = swz(m0w + (lane & 15), ((lane >> 4) & 1) * 16);
    const uint32_t bK0 = 16384 + swz(n0w + ((lane >> 4) & 1) * 8 + (lane & 7),
                                     ((lane >> 3) & 1) * 16);

    uint32_t afr[2][4][4], bfr[2][4][4];

    issue_stage(sm, 0, Ag, lda, Bg, ldb, 0);  CP_COMMIT();
    issue_stage(sm, 1, Ag, lda, Bg, ldb, 64); CP_COMMIT();

    for (int ks = 0; ks < nK; ks++) {
        CP_WAIT(1);
        __syncthreads();

        const uint32_t so = sm + (ks % 3) * STAGE_B;
        const uint32_t ab = so + aK0, bb = so + bK0;
        LDFRAGS(0, ab, bb);                       // kk=0 fragments

        if (ks + 2 < nK) issue_stage(sm, (ks + 2) % 3, Ag, lda, Bg, ldb, (ks + 2) * 64);
        CP_COMMIT();

#pragma unroll
        for (int kk = 0; kk < 4; kk++) {
            const int cur = kk & 1;
            if (kk < 3)
                LDFRAGS(cur ^ 1, ab ^ ((kk + 1) << 5), bb ^ ((kk + 1) << 5));
#pragma unroll
            for (int mt = 0; mt < 4; mt++)
#pragma unroll
                for (int n16 = 0; n16 < 4; n16++) {
                    MMA16816(acc[mt][2*n16],     afr[cur][mt], bfr[cur][n16][0], bfr[cur][n16][1]);
                    MMA16816(acc[mt][2*n16 + 1], afr[cur][mt], bfr[cur][n16][2], bfr[cur][n16][3]);
                }
        }
    }
    CP_WAIT(0);
    __syncthreads();
}

#define EPI_COORDS() \
    const int warp = threadIdx.x >> 5, lane = threadIdx.x & 31; \
    const int m0w = (warp & 1) * 64, n0w = (warp >> 1) * 64; \
    const int gm = lane >> 2, np = (lane & 3) * 2;

#define ACC_INIT() \
    float acc[4][8][4]; \
    _Pragma("unroll") for (int i = 0; i < 4; i++) \
    _Pragma("unroll") for (int j = 0; j < 8; j++) \
    _Pragma("unroll") for (int q = 0; q < 4; q++) acc[i][j][q] = 0.f;

#define SMEM_ALIGN128() \
    extern __shared__ char dynsm[]; \
    uint32_t sm = (smem_u32(dynsm) + 127u) & ~127u;

// ------------------------- fused QKV projection ------------------------------
__global__ __launch_bounds__(NTH, 1)
void qkv_mma_kernel(const float* __restrict__ bq, const float* __restrict__ bk,
                    const float* __restrict__ bv) {
    SMEM_ALIGN128();
    const int bx = blockIdx.x, by = blockIdx.y;   // n-tile (0..11), m-tile
    const int row0 = by * 128, col0 = bx * 256;   // col0 in [0, 3072)
    const int sel = bx >> 2;                      // 0=q 1=k 2=v
    const int vcol0 = col0 & 1023;
    const float* bias = (sel == 0) ? bq : (sel == 1) ? bk : bv;
    const float mul = (sel == 0) ? SCALE : 1.0f;

    ACC_INIT();
    const __half* Ag = g_xh + (size_t)row0 * CC;
    const __half* Bg = g_wt + (size_t)col0 * CC;
    gemm_mainloop(sm, Ag, CC, Bg, CC, CC / 64, acc);

    EPI_COORDS();
    if (sel != 2) {
        __half* O = (sel == 0 ? g_qh : g_kh);
#pragma unroll
        for (int mt = 0; mt < 4; mt++)
#pragma unroll
            for (int nt = 0; nt < 8; nt++) {
                int n = n0w + nt * 8 + np;
                float b0 = __ldg(bias + vcol0 + n), b1 = __ldg(bias + vcol0 + n + 1);
                int m = m0w + mt * 16 + gm;
                __half2 h0 = __floats2half2_rn((acc[mt][nt][0] + b0) * mul,
                                               (acc[mt][nt][1] + b1) * mul);
                __half2 h1 = __floats2half2_rn((acc[mt][nt][2] + b0) * mul,
                                               (acc[mt][nt][3] + b1) * mul);
                *(uint32_t*)(O + (size_t)(row0 + m) * CC + vcol0 + n)     = *(uint32_t*)&h0;
                *(uint32_t*)(O + (size_t)(row0 + m + 8) * CC + vcol0 + n) = *(uint32_t*)&h1;
            }
    } else {
        // V: transpose via smem staging -> g_vt[c][token]
        __half* stage = (__half*)dynsm;          // [256][136]
#pragma unroll
        for (int mt = 0; mt < 4; mt++)
#pragma unroll
            for (int nt = 0; nt < 8; nt++) {
                int n = n0w + nt * 8 + np;
                float b0 = __ldg(bias + vcol0 + n), b1 = __ldg(bias + vcol0 + n + 1);
                int m = m0w + mt * 16 + gm;
                stage[(size_t)n * 136 + m]           = __float2half(acc[mt][nt][0] + b0);
                stage[(size_t)(n + 1) * 136 + m]     = __float2half(acc[mt][nt][1] + b1);
                stage[(size_t)n * 136 + m + 8]       = __float2half(acc[mt][nt][2] + b0);
                stage[(size_t)(n + 1) * 136 + m + 8] = __float2half(acc[mt][nt][3] + b1);
            }
        __syncthreads();
        const int z = row0 >> 11, tok0 = row0 & (TT - 1);
        // 256 c-rows of 128 token-halfs: one row per thread, 16 x 16B
        const int r = threadIdx.x;
        const uint4* srcrow = (const uint4*)(stage + (size_t)r * 136);
        __half* dst = g_vt + ((size_t)z * CC + vcol0 + r) * TT + tok0;
#pragma unroll
        for (int i = 0; i < 16; i++)
            ((uint4*)dst)[i] = srcrow[i];
    }
}

// ------------------------- scores (q prescaled) ------------------------------
__global__ __launch_bounds__(NTH, 1)
void scores_mma_kernel() {
    const int bx = blockIdx.x, by = blockIdx.y, z = blockIdx.z;
    if (bx * 2 > by) return;                    // causal tile skip (256-wide s)
    SMEM_ALIGN128();
    const int t0 = by * 128, s0 = bx * 256;

    ACC_INIT();
    const __half* Ag = g_qh + ((size_t)z * TT + t0) * CC;
    const __half* Bg = g_kh + ((size_t)z * TT + s0) * CC;
    gemm_mainloop(sm, Ag, CC, Bg, CC, CC / 64, acc);

    EPI_COORDS();
    float* S = g_s + ((size_t)z * TT + t0) * TT + s0;
#pragma unroll
    for (int mt = 0; mt < 4; mt++)
#pragma unroll
        for (int nt = 0; nt < 8; nt++) {
            int m = m0w + mt * 16 + gm, n = n0w + nt * 8 + np;
            *(float2*)(S + (size_t)m * TT + n)       = make_float2(acc[mt][nt][0], acc[mt][nt][1]);
            *(float2*)(S + (size_t)(m + 8) * TT + n) = make_float2(acc[mt][nt][2], acc[mt][nt][3]);
        }
}

// ------------------------- softmax: warp per row -----------------------------
__global__ __launch_bounds__(256)
void softmax_kernel() {
    extern __shared__ float shall[];            // 8 rows x 2048 floats
    const int warp = threadIdx.x >> 5, lane = threadIdx.x & 31;
    const int row = blockIdx.x * 8 + warp;
    const int z = row >> 11;
    const int t = row & (TT - 1);
    const size_t off = ((size_t)z * TT + t) * TT;
    const float4* __restrict__ S4 = (const float4*)(g_s + off);
    float* sh = shall + warp * TT;
    const int n = t + 1;
    const int nch = (n + 3) >> 2;

    float mx = -INFINITY;
    for (int c = lane; c < nch; c += 32) {
        float4 v = S4[c];
        int base = c * 4;
        if (base + 3 >= n) {
            if (base + 1 >= n) v.y = -INFINITY;
            if (base + 2 >= n) v.z = -INFINITY;
            if (base + 3 >= n) v.w = -INFINITY;
        }
        ((float4*)sh)[c] = v;
        mx = fmaxf(mx, fmaxf(fmaxf(v.x, v.y), fmaxf(v.z, v.w)));
    }
#pragma unroll
    for (int o = 16; o > 0; o >>= 1)
        mx = fmaxf(mx, __shfl_xor_sync(0xFFFFFFFFu, mx, o));

    float sum = 0.f;
    for (int c = lane; c < nch; c += 32) {
        float4 v = ((float4*)sh)[c];
        v.x = __expf(v.x - mx); v.y = __expf(v.y - mx);
        v.z = __expf(v.z - mx); v.w = __expf(v.w - mx);
        ((float4*)sh)[c] = v;
        sum += v.x + v.y + v.z + v.w;
    }
#pragma unroll
    for (int o = 16; o > 0; o >>= 1)
        sum += __shfl_xor_sync(0xFFFFFFFFu, sum, o);
    const float inv = 1.f / sum;
    __syncwarp();

    const int zEnd = ((t >> 7) + 1) << 7;       // pad to 128-tile boundary
    __half* P = g_ph + off;
    for (int c = lane; c < (zEnd >> 3); c += 32) {
        int i0 = c * 8;
        __half h[8];
#pragma unroll
        for (int j = 0; j < 8; j++) {
            int idx = i0 + j;
            h[j] = __float2half((idx < n) ? sh[idx] * inv : 0.f);
        }
        *(uint4*)(P + i0) = *(uint4*)h;
    }
}

// ------------------------- P @ V (heavy tiles first) -------------------------
__global__ __launch_bounds__(NTH, 1)
void pv_mma_kernel(float* __restrict__ Out) {
    const int bx = blockIdx.x, by = 15 - blockIdx.y, z = blockIdx.z;
    SMEM_ALIGN128();
    const int t0 = by * 128, c0 = bx * 256;

    ACC_INIT();
    const __half* Ag = g_ph + ((size_t)z * TT + t0) * TT;
    const __half* Bg = g_vt + ((size_t)z * CC + c0) * TT;
    gemm_mainloop(sm, Ag, TT, Bg, TT, (by + 1) * 2, acc);   // causal truncation

    EPI_COORDS();
    float* O = Out + ((size_t)z * TT + t0) * CC + c0;
#pragma unroll
    for (int mt = 0; mt < 4; mt++)
#pragma unroll
        for (int nt = 0; nt < 8; nt++) {
            int m = m0w + mt * 16 + gm, n = n0w + nt * 8 + np;
            *(float2*)(O + (size_t)m * CC + n)       = make_float2(acc[mt][nt][0], acc[mt][nt][1]);
            *(float2*)(O + (size_t)(m + 8) * CC + n) = make_float2(acc[mt][nt][2], acc[mt][nt][3]);
        }
}

// ------------------------- launch -------------------------------------------
extern "C" void kernel_launch(void* const* d_in, const int* in_sizes, int n_in,
                              void* d_out, int out_size) {
    const float* x  = (const float*)d_in[0];
    const float* Wq = (const float*)d_in[1];
    const float* bq = (const float*)d_in[2];
    const float* Wk = (const float*)d_in[3];
    const float* bk = (const float*)d_in[4];
    const float* Wv = (const float*)d_in[5];
    const float* bv = (const float*)d_in[6];
    float* out = (float*)d_out;

    cudaFuncSetAttribute(qkv_mma_kernel,    cudaFuncAttributeMaxDynamicSharedMemorySize, DYN_B);
    cudaFuncSetAttribute(scores_mma_kernel, cudaFuncAttributeMaxDynamicSharedMemorySize, DYN_B);
    cudaFuncSetAttribute(pv_mma_kernel,     cudaFuncAttributeMaxDynamicSharedMemorySize, DYN_B);
    cudaFuncSetAttribute(softmax_kernel,    cudaFuncAttributeMaxDynamicSharedMemorySize, 65536);

    convert_x_kernel<<<MTOT * CC / 4 / 256, 256>>>(x);
    convert_w_kernel<<<dim3(32, 32, 3), dim3(32, 8)>>>(Wq, Wk, Wv);

    qkv_mma_kernel<<<dim3(12, 64), NTH, DYN_B>>>(bq, bk, bv);

    scores_mma_kernel<<<dim3(8, 16, 4), NTH, DYN_B>>>();
    softmax_kernel<<<BB * TT / 8, 256, 65536>>>();
    pv_mma_kernel<<<dim3(4, 16, 4), NTH, DYN_B>>>(out);
}

// round 8
// speedup vs baseline: 9.5186x; 1.1205x over previous
#include <cuda_runtime.h>
#include <cuda_fp16.h>
#include <cstdint>
#include <math.h>

#define BB 4
#define TT 2048
#define CC 1024
#define MTOT (BB*TT)
#define SCALE 0.03125f

#define NTH 128
#define STAGE_B 32768      // A 16KB (128x64) + B 16KB (128x64) per stage
#define STAGES 3
#define DYN_B (STAGES*STAGE_B + 128)   // +128 for 128B alignment

// ------------------------- device scratch (no allocs) -----------------------
__device__ __half g_xh[MTOT*CC];                    // x fp16
__device__ __half g_wt[3*CC*CC];                    // W^T fp16  [sel*1024+n][k]
__device__ __half g_qh[MTOT*CC];                    // q * SCALE
__device__ __half g_kh[MTOT*CC];
__device__ __half g_vt[(size_t)BB*CC*TT];           // V^T per batch [c][token]
__device__ float  g_s[(size_t)BB*TT*TT];            // scores fp32
__device__ __half g_ph[(size_t)BB*TT*TT];           // probs fp16

// ------------------------- ptx helpers --------------------------------------
__device__ __forceinline__ uint32_t smem_u32(const void* p) {
    uint32_t a;
    asm("{ .reg .u64 t; cvta.to.shared.u64 t, %1; cvt.u32.u64 %0, t; }" : "=r"(a) : "l"(p));
    return a;
}
#define CP_ASYNC16(dst, src) \
    asm volatile("cp.async.cg.shared.global [%0], [%1], 16;" :: "r"(dst), "l"(src))
#define CP_COMMIT() asm volatile("cp.async.commit_group;" ::: "memory")
#define CP_WAIT(n)  asm volatile("cp.async.wait_group %0;" :: "n"(n) : "memory")
#define LDSM4(r0,r1,r2,r3,addr) \
    asm volatile("ldmatrix.sync.aligned.m8n8.x4.shared.b16 {%0,%1,%2,%3}, [%4];" \
        : "=r"(r0),"=r"(r1),"=r"(r2),"=r"(r3) : "r"(addr))
#define MMA16816(c, a, b0, b1) \
    asm volatile("mma.sync.aligned.m16n8k16.row.col.f32.f16.f16.f32 " \
        "{%0,%1,%2,%3}, {%4,%5,%6,%7}, {%8,%9}, {%0,%1,%2,%3};" \
        : "+f"((c)[0]), "+f"((c)[1]), "+f"((c)[2]), "+f"((c)[3]) \
        : "r"((a)[0]), "r"((a)[1]), "r"((a)[2]), "r"((a)[3]), "r"(b0), "r"(b1))

// swizzle for 128B rows (64 fp16): seg(16B) ^= row&7 — conflict-free for
// cp.async 16B fills and all ldmatrix phases
__device__ __forceinline__ uint32_t swz(uint32_t row, uint32_t byteoff) {
    uint32_t seg = (byteoff >> 4) ^ (row & 7);
    return row * 128 + (seg << 4) + (byteoff & 15);
}

// ------------------------- converts -----------------------------------------
__global__ void convert_x_kernel(const float* __restrict__ x) {
    size_t i = (size_t)blockIdx.x * 256 + threadIdx.x;
    float4 v = ((const float4*)x)[i];
    __half2 h0 = __floats2half2_rn(v.x, v.y);
    __half2 h1 = __floats2half2_rn(v.z, v.w);
    ((uint2*)g_xh)[i] = make_uint2(*(uint32_t*)&h0, *(uint32_t*)&h1);
}

// W[k][n] -> wt[n][k] fp16 ; blockIdx.z selects q/k/v
__global__ void convert_w_kernel(const float* __restrict__ Wq,
                                 const float* __restrict__ Wk,
                                 const float* __restrict__ Wv) {
    __shared__ float tile[32][33];
    const int sel = blockIdx.z;
    const float* W = (sel == 0) ? Wq : (sel == 1) ? Wk : Wv;
    int bx = blockIdx.x * 32, by = blockIdx.y * 32;
    int tx = threadIdx.x, ty = threadIdx.y;    // 32 x 8
#pragma unroll
    for (int r = 0; r < 4; r++)
        tile[ty + 8*r][tx] = W[(size_t)(by + ty + 8*r) * CC + bx + tx];
    __syncthreads();
    __half* dst = g_wt + (size_t)sel * CC * CC;
#pragma unroll
    for (int r = 0; r < 4; r++)
        dst[(size_t)(bx + ty + 8*r) * CC + by + tx] = __float2half(tile[tx][ty + 8*r]);
}

// ------------------------- pipelined MMA mainloop (128x128, BK=64) -----------
__device__ __forceinline__ void issue_stage(uint32_t sm, int stage,
                                            const __half* __restrict__ Ag, int lda,
                                            const __half* __restrict__ Bg, int ldb, int k0) {
    const int tid = threadIdx.x;
    uint32_t sb = sm + stage * STAGE_B;
#pragma unroll
    for (int i = 0; i < 8; i++) {              // A: 128 rows x 8 segs of 16B
        int c = tid + i * 128;
        int row = c >> 3, seg = c & 7;
        CP_ASYNC16(sb + swz(row, seg * 16), Ag + (size_t)row * lda + k0 + seg * 8);
    }
#pragma unroll
    for (int i = 0; i < 8; i++) {              // B: 128 rows
        int c = tid + i * 128;
        int row = c >> 3, seg = c & 7;
        CP_ASYNC16(sb + 16384 + swz(row, seg * 16), Bg + (size_t)row * ldb + k0 + seg * 8);
    }
}

// acc[4][8][4]: warp tile 64(m) x 64(n); 4 warps as 2x2 (m x n)
__device__ __forceinline__ void gemm_mainloop(uint32_t sm,
                                              const __half* __restrict__ Ag, int lda,
                                              const __half* __restrict__ Bg, int ldb,
                                              int nK, float acc[4][8][4]) {
    const int tid  = threadIdx.x;
    const int warp = tid >> 5, lane = tid & 31;
    const int m0w = (warp & 1) * 64, n0w = (warp >> 1) * 64;

    // kk=0 base offsets; addr(kk) = base ^ (kk<<5) (seg-field XOR identity;
    // requires sm 128B-aligned, STAGE_B % 128 == 0)
    const uint32_t aK0 = swz(m0w + (lane & 15), ((lane >> 4) & 1) * 16);
    const uint32_t bK0 = 16384 + swz(n0w + ((lane >> 4) & 1) * 8 + (lane & 7),
                                     ((lane >> 3) & 1) * 16);

    issue_stage(sm, 0, Ag, lda, Bg, ldb, 0);  CP_COMMIT();
    issue_stage(sm, 1, Ag, lda, Bg, ldb, 64); CP_COMMIT();

    for (int ks = 0; ks < nK; ks++) {
        CP_WAIT(1);
        __syncthreads();
        if (ks + 2 < nK) issue_stage(sm, (ks + 2) % 3, Ag, lda, Bg, ldb, (ks + 2) * 64);
        CP_COMMIT();

        const uint32_t so = sm + (ks % 3) * STAGE_B;
        const uint32_t ab = so + aK0, bb = so + bK0;
#pragma unroll
        for (int kk = 0; kk < 4; kk++) {
            uint32_t a[4][4], b[4][4];
            const uint32_t x = (uint32_t)(kk << 5);
#pragma unroll
            for (int mt = 0; mt < 4; mt++)
                LDSM4(a[mt][0], a[mt][1], a[mt][2], a[mt][3], (ab ^ x) + mt * 2048);
#pragma unroll
            for (int n16 = 0; n16 < 4; n16++)
                LDSM4(b[n16][0], b[n16][1], b[n16][2], b[n16][3], (bb ^ x) + n16 * 2048);
#pragma unroll
            for (int mt = 0; mt < 4; mt++)
#pragma unroll
                for (int n16 = 0; n16 < 4; n16++) {
                    MMA16816(acc[mt][2*n16],     a[mt], b[n16][0], b[n16][1]);
                    MMA16816(acc[mt][2*n16 + 1], a[mt], b[n16][2], b[n16][3]);
                }
        }
    }
    CP_WAIT(0);
    __syncthreads();
}

#define EPI_COORDS() \
    const int warp = threadIdx.x >> 5, lane = threadIdx.x & 31; \
    const int m0w = (warp & 1) * 64, n0w = (warp >> 1) * 64; \
    const int gm = lane >> 2, np = (lane & 3) * 2;

#define ACC_INIT() \
    float acc[4][8][4]; \
    _Pragma("unroll") for (int i = 0; i < 4; i++) \
    _Pragma("unroll") for (int j = 0; j < 8; j++) \
    _Pragma("unroll") for (int q = 0; q < 4; q++) acc[i][j][q] = 0.f;

#define SMEM_ALIGN128() \
    extern __shared__ char dynsm[]; \
    uint32_t sm = (smem_u32(dynsm) + 127u) & ~127u;

// ------------------------- fused QKV projection ------------------------------
__global__ __launch_bounds__(NTH, 2)
void qkv_mma_kernel(const float* __restrict__ bq, const float* __restrict__ bk,
                    const float* __restrict__ bv) {
    SMEM_ALIGN128();
    const int bx = blockIdx.x, by = blockIdx.y;   // n-tile (0..23), m-tile
    const int row0 = by * 128, col0 = bx * 128;   // col0 in [0, 3072)
    const int sel = bx >> 3;                      // 0=q 1=k 2=v
    const int vcol0 = col0 & 1023;
    const float* bias = (sel == 0) ? bq : (sel == 1) ? bk : bv;
    const float mul = (sel == 0) ? SCALE : 1.0f;

    ACC_INIT();
    const __half* Ag = g_xh + (size_t)row0 * CC;
    const __half* Bg = g_wt + (size_t)col0 * CC;
    gemm_mainloop(sm, Ag, CC, Bg, CC, CC / 64, acc);

    EPI_COORDS();
    if (sel != 2) {
        __half* O = (sel == 0 ? g_qh : g_kh);
#pragma unroll
        for (int mt = 0; mt < 4; mt++)
#pragma unroll
            for (int nt = 0; nt < 8; nt++) {
                int n = n0w + nt * 8 + np;
                float b0 = __ldg(bias + vcol0 + n), b1 = __ldg(bias + vcol0 + n + 1);
                int m = m0w + mt * 16 + gm;
                __half2 h0 = __floats2half2_rn((acc[mt][nt][0] + b0) * mul,
                                               (acc[mt][nt][1] + b1) * mul);
                __half2 h1 = __floats2half2_rn((acc[mt][nt][2] + b0) * mul,
                                               (acc[mt][nt][3] + b1) * mul);
                *(uint32_t*)(O + (size_t)(row0 + m) * CC + vcol0 + n)     = *(uint32_t*)&h0;
                *(uint32_t*)(O + (size_t)(row0 + m + 8) * CC + vcol0 + n) = *(uint32_t*)&h1;
            }
    } else {
        // V: transpose via smem staging -> g_vt[c][token]
        __half* stage = (__half*)dynsm;          // [128][136]
#pragma unroll
        for (int mt = 0; mt < 4; mt++)
#pragma unroll
            for (int nt = 0; nt < 8; nt++) {
                int n = n0w + nt * 8 + np;
                float b0 = __ldg(bias + vcol0 + n), b1 = __ldg(bias + vcol0 + n + 1);
                int m = m0w + mt * 16 + gm;
                stage[(size_t)n * 136 + m]           = __float2half(acc[mt][nt][0] + b0);
                stage[(size_t)(n + 1) * 136 + m]     = __float2half(acc[mt][nt][1] + b1);
                stage[(size_t)n * 136 + m + 8]       = __float2half(acc[mt][nt][2] + b0);
                stage[(size_t)(n + 1) * 136 + m + 8] = __float2half(acc[mt][nt][3] + b1);
            }
        __syncthreads();
        const int z = row0 >> 11, tok0 = row0 & (TT - 1);
        // 128 c-rows of 128 token-halfs: one row per thread, 16 x 16B
        const int r = threadIdx.x;
        const uint4* srcrow = (const uint4*)(stage + (size_t)r * 136);
        __half* dst = g_vt + ((size_t)z * CC + vcol0 + r) * TT + tok0;
#pragma unroll
        for (int i = 0; i < 16; i++)
            ((uint4*)dst)[i] = srcrow[i];
    }
}

// ------------------------- scores (q prescaled) ------------------------------
__global__ __launch_bounds__(NTH, 2)
void scores_mma_kernel() {
    const int bx = blockIdx.x, by = blockIdx.y, z = blockIdx.z;
    if (bx > by) return;                        // causal tile skip
    SMEM_ALIGN128();
    const int t0 = by * 128, s0 = bx * 128;

    ACC_INIT();
    const __half* Ag = g_qh + ((size_t)z * TT + t0) * CC;
    const __half* Bg = g_kh + ((size_t)z * TT + s0) * CC;
    gemm_mainloop(sm, Ag, CC, Bg, CC, CC / 64, acc);

    EPI_COORDS();
    float* S = g_s + ((size_t)z * TT + t0) * TT + s0;
#pragma unroll
    for (int mt = 0; mt < 4; mt++)
#pragma unroll
        for (int nt = 0; nt < 8; nt++) {
            int m = m0w + mt * 16 + gm, n = n0w + nt * 8 + np;
            *(float2*)(S + (size_t)m * TT + n)       = make_float2(acc[mt][nt][0], acc[mt][nt][1]);
            *(float2*)(S + (size_t)(m + 8) * TT + n) = make_float2(acc[mt][nt][2], acc[mt][nt][3]);
        }
}

// ------------------------- softmax: warp per row -----------------------------
__global__ __launch_bounds__(256)
void softmax_kernel() {
    extern __shared__ float shall[];            // 8 rows x 2048 floats
    const int warp = threadIdx.x >> 5, lane = threadIdx.x & 31;
    const int row = blockIdx.x * 8 + warp;
    const int z = row >> 11;
    const int t = row & (TT - 1);
    const size_t off = ((size_t)z * TT + t) * TT;
    const float4* __restrict__ S4 = (const float4*)(g_s + off);
    float* sh = shall + warp * TT;
    const int n = t + 1;
    const int nch = (n + 3) >> 2;

    float mx = -INFINITY;
    for (int c = lane; c < nch; c += 32) {
        float4 v = S4[c];
        int base = c * 4;
        if (base + 3 >= n) {
            if (base + 1 >= n) v.y = -INFINITY;
            if (base + 2 >= n) v.z = -INFINITY;
            if (base + 3 >= n) v.w = -INFINITY;
        }
        ((float4*)sh)[c] = v;
        mx = fmaxf(mx, fmaxf(fmaxf(v.x, v.y), fmaxf(v.z, v.w)));
    }
#pragma unroll
    for (int o = 16; o > 0; o >>= 1)
        mx = fmaxf(mx, __shfl_xor_sync(0xFFFFFFFFu, mx, o));

    float sum = 0.f;
    for (int c = lane; c < nch; c += 32) {
        float4 v = ((float4*)sh)[c];
        v.x = __expf(v.x - mx); v.y = __expf(v.y - mx);
        v.z = __expf(v.z - mx); v.w = __expf(v.w - mx);
        ((float4*)sh)[c] = v;
        sum += v.x + v.y + v.z + v.w;
    }
#pragma unroll
    for (int o = 16; o > 0; o >>= 1)
        sum += __shfl_xor_sync(0xFFFFFFFFu, sum, o);
    const float inv = 1.f / sum;
    __syncwarp();

    const int zEnd = ((t >> 7) + 1) << 7;       // pad to 128-tile boundary
    __half* P = g_ph + off;
    for (int c = lane; c < (zEnd >> 3); c += 32) {
        int i0 = c * 8;
        __half h[8];
#pragma unroll
        for (int j = 0; j < 8; j++) {
            int idx = i0 + j;
            h[j] = __float2half((idx < n) ? sh[idx] * inv : 0.f);
        }
        *(uint4*)(P + i0) = *(uint4*)h;
    }
}

// ------------------------- P @ V (heavy tiles first) -------------------------
__global__ __launch_bounds__(NTH, 2)
void pv_mma_kernel(float* __restrict__ Out) {
    const int bx = blockIdx.x, by = 15 - blockIdx.y, z = blockIdx.z;
    SMEM_ALIGN128();
    const int t0 = by * 128, c0 = bx * 128;

    ACC_INIT();
    const __half* Ag = g_ph + ((size_t)z * TT + t0) * TT;
    const __half* Bg = g_vt + ((size_t)z * CC + c0) * TT;
    gemm_mainloop(sm, Ag, TT, Bg, TT, (by + 1) * 2, acc);   // causal truncation

    EPI_COORDS();
    float* O = Out + ((size_t)z * TT + t0) * CC + c0;
#pragma unroll
    for (int mt = 0; mt < 4; mt++)
#pragma unroll
        for (int nt = 0; nt < 8; nt++) {
            int m = m0w + mt * 16 + gm, n = n0w + nt * 8 + np;
            *(float2*)(O + (size_t)m * CC + n)       = make_float2(acc[mt][nt][0], acc[mt][nt][1]);
            *(float2*)(O + (size_t)(m + 8) * CC + n) = make_float2(acc[mt][nt][2], acc[mt][nt][3]);
        }
}

// ------------------------- launch -------------------------------------------
extern "C" void kernel_launch(void* const* d_in, const int* in_sizes, int n_in,
                              void* d_out, int out_size) {
    const float* x  = (const float*)d_in[0];
    const float* Wq = (const float*)d_in[1];
    const float* bq = (const float*)d_in[2];
    const float* Wk = (const float*)d_in[3];
    const float* bk = (const float*)d_in[4];
    const float* Wv = (const float*)d_in[5];
    const float* bv = (const float*)d_in[6];
    float* out = (float*)d_out;

    cudaFuncSetAttribute(qkv_mma_kernel,    cudaFuncAttributeMaxDynamicSharedMemorySize, DYN_B);
    cudaFuncSetAttribute(scores_mma_kernel, cudaFuncAttributeMaxDynamicSharedMemorySize, DYN_B);
    cudaFuncSetAttribute(pv_mma_kernel,     cudaFuncAttributeMaxDynamicSharedMemorySize, DYN_B);
    cudaFuncSetAttribute(softmax_kernel,    cudaFuncAttributeMaxDynamicSharedMemorySize, 65536);

    convert_x_kernel<<<MTOT * CC / 4 / 256, 256>>>(x);
    convert_w_kernel<<<dim3(32, 32, 3), dim3(32, 8)>>>(Wq, Wk, Wv);

    qkv_mma_kernel<<<dim3(24, 64), NTH, DYN_B>>>(bq, bk, bv);

    scores_mma_kernel<<<dim3(16, 16, 4), NTH, DYN_B>>>();
    softmax_kernel<<<BB * TT / 8, 256, 65536>>>();
    pv_mma_kernel<<<dim3(8, 16, 4), NTH, DYN_B>>>(out);
}